// round 13
// baseline (speedup 1.0000x reference)
#include <cuda_runtime.h>
#include <cuda_bf16.h>
#include <cstdint>

#define BB 16
#define TT 2048
#define CC 512
#define HH 64
#define SCALE 0.125f

// Q,K split bf16 (packed pairs), row-major [b*T + t][64]
__device__ __nv_bfloat16 g_qh[BB * TT * HH];
__device__ __nv_bfloat16 g_ql[BB * TT * HH];
__device__ __nv_bfloat16 g_kh[BB * TT * HH];
__device__ __nv_bfloat16 g_kl[BB * TT * HH];
// V split + transposed: [b*64 + h][t]
__device__ __nv_bfloat16 g_vth[BB * HH * TT];
__device__ __nv_bfloat16 g_vtl[BB * HH * TT];
// Er split: [r][64]
__device__ __nv_bfloat16 g_erh[TT * HH];
__device__ __nv_bfloat16 g_erl[TT * HH];
// W transposed+split: [n (0..191)][k (0..511)]
__device__ __nv_bfloat16 g_wth[192 * 512];
__device__ __nv_bfloat16 g_wtl[192 * 512];

__device__ __forceinline__ void pk(float x, float y, uint32_t& h, uint32_t& l) {
  __nv_bfloat16 hx = __float2bfloat16(x), hy = __float2bfloat16(y);
  float rx = x - __bfloat162float(hx), ry = y - __bfloat162float(hy);
  __nv_bfloat16 lx = __float2bfloat16(rx), ly = __float2bfloat16(ry);
  h = (uint32_t)__bfloat16_as_ushort(hx) |
      ((uint32_t)__bfloat16_as_ushort(hy) << 16);
  l = (uint32_t)__bfloat16_as_ushort(lx) |
      ((uint32_t)__bfloat16_as_ushort(ly) << 16);
}
__device__ __forceinline__ void pk1(float x, __nv_bfloat16& h,
                                    __nv_bfloat16& l) {
  h = __float2bfloat16(x);
  l = __float2bfloat16(x - __bfloat162float(h));
}

__device__ __forceinline__ void mma16(float* c, uint32_t a0, uint32_t a1,
                                      uint32_t a2, uint32_t a3, uint32_t b0,
                                      uint32_t b1) {
  asm volatile(
      "mma.sync.aligned.m16n8k16.row.col.f32.bf16.bf16.f32 "
      "{%0,%1,%2,%3}, {%4,%5,%6,%7}, {%8,%9}, {%0,%1,%2,%3};"
      : "+f"(c[0]), "+f"(c[1]), "+f"(c[2]), "+f"(c[3])
      : "r"(a0), "r"(a1), "r"(a2), "r"(a3), "r"(b0), "r"(b1));
}
__device__ __forceinline__ void mmax2(float* c, const uint32_t* ah,
                                      const uint32_t* al, uint32_t bh0,
                                      uint32_t bh1, uint32_t bl0,
                                      uint32_t bl1) {
  mma16(c, ah[0], ah[1], ah[2], ah[3], bl0, bl1);
  mma16(c, al[0], al[1], al[2], al[3], bh0, bh1);
  mma16(c, ah[0], ah[1], ah[2], ah[3], bh0, bh1);
}

__device__ __forceinline__ void ldm4(uint32_t& r0, uint32_t& r1, uint32_t& r2,
                                     uint32_t& r3, uint32_t addr) {
  asm volatile(
      "ldmatrix.sync.aligned.m8n8.x4.shared.b16 {%0,%1,%2,%3}, [%4];"
      : "=r"(r0), "=r"(r1), "=r"(r2), "=r"(r3)
      : "r"(addr));
}
__device__ __forceinline__ uint32_t sptr(const void* p) {
  return (uint32_t)__cvta_generic_to_shared(p);
}

// ---------------------------------------------------------------------------
// One-shot preps
// ---------------------------------------------------------------------------
__global__ __launch_bounds__(256) void prep_w(const float* __restrict__ Wq,
                                              const float* __restrict__ Wk,
                                              const float* __restrict__ Wv) {
  int idx = blockIdx.x * 256 + threadIdx.x;
  int n = idx >> 9, k = idx & 511;
  const float* Wm = n < 64 ? Wq : (n < 128 ? Wk : Wv);
  float v = Wm[(size_t)k * HH + (n & 63)];
  __nv_bfloat16 h, l;
  pk1(v, h, l);
  g_wth[idx] = h;
  g_wtl[idx] = l;
}

__global__ __launch_bounds__(256) void prep_er(const float* __restrict__ Er) {
  int idx = blockIdx.x * 256 + threadIdx.x;
  __nv_bfloat16 h, l;
  pk1(Er[idx], h, l);
  g_erh[idx] = h;
  g_erl[idx] = l;
}

// ---------------------------------------------------------------------------
// QKV projection (unchanged).
// ---------------------------------------------------------------------------
#define WX 36
#define WW 36
#define QKV_WORDS (2 * 64 * WX + 2 * 192 * WW)
__global__ __launch_bounds__(256) void qkv_mma(const float* __restrict__ x) {
  extern __shared__ uint32_t qsm[];
  uint32_t* Xh = qsm;
  uint32_t* Xl = Xh + 64 * WX;
  uint32_t* WTh = Xl + 64 * WX;
  uint32_t* WTl = WTh + 192 * WW;
  int tid = threadIdx.x, w = tid >> 5, lane = tid & 31;
  int g = lane >> 2, tg = lane & 3;
  int row0 = blockIdx.x * 64;
  int mt = w & 3, nh = w >> 2;
  float acc[12][4] = {};

  for (int k0 = 0; k0 < CC; k0 += 64) {
    __syncthreads();
    for (int i = tid; i < 1024; i += 256) {
      int r = i >> 4, h4 = (i & 15) << 2;
      float4 v4 = *(const float4*)&x[(size_t)(row0 + r) * CC + k0 + h4];
      uint32_t h01, l01, h23, l23;
      pk(v4.x, v4.y, h01, l01);
      pk(v4.z, v4.w, h23, l23);
      int wc = r * WX + (h4 >> 1);
      *(uint2*)&Xh[wc] = make_uint2(h01, h23);
      *(uint2*)&Xl[wc] = make_uint2(l01, l23);
    }
    for (int i = tid; i < 1536; i += 256) {
      int n = i >> 3, w4 = (i & 7) << 2;
      int src = n * 256 + (k0 >> 1) + w4;
      *(uint4*)&WTh[n * WW + w4] = *(const uint4*)((const uint32_t*)g_wth + src);
      *(uint4*)&WTl[n * WW + w4] = *(const uint4*)((const uint32_t*)g_wtl + src);
    }
    __syncthreads();
    int r1 = 16 * mt + g, r2 = r1 + 8;
#pragma unroll
    for (int c4 = 0; c4 < 4; c4++) {
      int kw = 8 * c4;
      uint32_t ah[4], al[4];
      ah[0] = Xh[r1 * WX + kw + tg];
      ah[1] = Xh[r2 * WX + kw + tg];
      ah[2] = Xh[r1 * WX + kw + 4 + tg];
      ah[3] = Xh[r2 * WX + kw + 4 + tg];
      al[0] = Xl[r1 * WX + kw + tg];
      al[1] = Xl[r2 * WX + kw + tg];
      al[2] = Xl[r1 * WX + kw + 4 + tg];
      al[3] = Xl[r2 * WX + kw + 4 + tg];
#pragma unroll
      for (int v = 0; v < 12; v++) {
        int n = 8 * (12 * nh + v) + g;
        uint32_t bh0 = WTh[n * WW + kw + tg];
        uint32_t bh1 = WTh[n * WW + kw + 4 + tg];
        uint32_t bl0 = WTl[n * WW + kw + tg];
        uint32_t bl1 = WTl[n * WW + kw + 4 + tg];
        mmax2(acc[v], ah, al, bh0, bh1, bl0, bl1);
      }
    }
  }
  int r0g = row0 + 16 * mt + g;
#pragma unroll
  for (int v = 0; v < 12; v++) {
    int ncol = 8 * (12 * nh + v) + 2 * tg;
    int m = ncol >> 6, nn = ncol & 63;
    if (m < 2) {
      uint32_t* oh = (uint32_t*)(m == 0 ? g_qh : g_kh);
      uint32_t* ol = (uint32_t*)(m == 0 ? g_ql : g_kl);
      uint32_t h, l;
      pk(acc[v][0], acc[v][1], h, l);
      oh[(size_t)r0g * 32 + (nn >> 1)] = h;
      ol[(size_t)r0g * 32 + (nn >> 1)] = l;
      pk(acc[v][2], acc[v][3], h, l);
      oh[(size_t)(r0g + 8) * 32 + (nn >> 1)] = h;
      ol[(size_t)(r0g + 8) * 32 + (nn >> 1)] = l;
    } else {
      int bidx = r0g >> 11, t = r0g & 2047;
      size_t base = ((size_t)bidx * HH + nn) * TT + t;
      __nv_bfloat16 h, l;
      pk1(acc[v][0], h, l);
      g_vth[base] = h;
      g_vtl[base] = l;
      pk1(acc[v][1], h, l);
      g_vth[base + TT] = h;
      g_vtl[base + TT] = l;
      pk1(acc[v][2], h, l);
      g_vth[base + 8] = h;
      g_vtl[base + 8] = l;
      pk1(acc[v][3], h, l);
      g_vth[base + TT + 8] = h;
      g_vtl[base + TT + 8] = l;
    }
  }
}

// ---------------------------------------------------------------------------
// Fused attention: producer/consumer pipeline.
//   S-warps 0-3: S-GEMM -> register softmax -> AV from registers (own rows).
//   G-warps 4-7: G-GEMM -> prefetch next iteration's tiles.
// 2 syncthreads per iteration. Vt double-buffered.
// ---------------------------------------------------------------------------
#define WB 36
#define WP 20
#define PG 104
#define VT_BUF (64 * WP)
#define ATTN_WORDS                                                    \
  (2 * 64 * WB + 4 * 32 * WB + 2 * 96 * WB + 2 * 2 * VT_BUF + 32 * PG + 64)

__global__ __launch_bounds__(256, 2) void attn_mma(
    const float* __restrict__ Er, float* __restrict__ out) {
  extern __shared__ uint32_t sm[];
  uint32_t* Qh = sm;
  uint32_t* Ql = Qh + 64 * WB;
  uint32_t* Kh = Ql + 64 * WB;
  uint32_t* Kl = Kh + 32 * WB;
  uint32_t* Qrh = Kl + 32 * WB;
  uint32_t* Qrl = Qrh + 32 * WB;
  uint32_t* Erh = Qrl + 32 * WB;
  uint32_t* Erl = Erh + 96 * WB;
  uint32_t* Vth = Erl + 96 * WB;        // [2][64][WP]
  uint32_t* Vtl = Vth + 2 * VT_BUF;     // [2][64][WP]
  float* Gs = (float*)(Vtl + 2 * VT_BUF);  // 32 x PG
  float* ds = Gs + 32 * PG;                // 64

  int tid = threadIdx.x, w = tid >> 5, lane = tid & 31;
  int g = lane >> 2, tg = lane & 3;
  int b = blockIdx.y;
  const uint4* QH4 = (const uint4*)g_qh + (size_t)b * TT * 8;
  const uint4* QL4 = (const uint4*)g_ql + (size_t)b * TT * 8;
  const uint4* KH4 = (const uint4*)g_kh + (size_t)b * TT * 8;
  const uint4* KL4 = (const uint4*)g_kl + (size_t)b * TT * 8;
  const uint4* VTH4 = (const uint4*)g_vth + (size_t)b * HH * 256;
  const uint4* VTL4 = (const uint4*)g_vtl + (size_t)b * HH * 256;
  const uint4* EH4 = (const uint4*)g_erh;
  const uint4* EL4 = (const uint4*)g_erl;

  bool sWarp = w < 4;
  int ws = w & 3;

  // ldmatrix lane-address components (byte offsets)
  int lrowA = lane & 15;
  int lcolA = ((lane >> 4) << 2);
  int lrowB = (lane & 7) + ((lane >> 4) << 3);
  int lcolB = ((lane >> 3) & 1) << 2;
  uint32_t aQh = sptr(Qh) + ((16 * ws + lrowA) * WB + lcolA) * 4;
  uint32_t aQl = aQh + (uint32_t)(64 * WB * 4);
  uint32_t bKh = sptr(Kh) + (lrowB * WB + lcolB) * 4;
  uint32_t bKl = bKh + (uint32_t)(32 * WB * 4);
  int mt2 = ws & 1, cg = ws >> 1;
  uint32_t aRh = sptr(Qrh) + ((16 * mt2 + lrowA) * WB + lcolA) * 4;
  uint32_t aRl = aRh + (uint32_t)(32 * WB * 4);
  uint32_t bEh = sptr(Erh) + ((48 * cg + lrowB) * WB + lcolB) * 4;
  uint32_t bEl = bEh + (uint32_t)(96 * WB * 4);
  uint32_t bVh0 = sptr(Vth) + (lrowB * WP + lcolB) * 4;
  uint32_t bVl0 = bVh0 + (uint32_t)(2 * VT_BUF * 4);

  for (int half = 0; half < 2; half++) {
    int t0 = half == 0 ? blockIdx.x * 64 : (TT - 64 - blockIdx.x * 64);
    __syncthreads();
    for (int i = tid; i < 1024; i += 256) {  // Q tile
      int hl = i >> 9, rem = i & 511;
      int r = rem >> 3, k4 = (rem & 7) << 2;
      const uint4* src = hl ? QL4 : QH4;
      uint32_t* dst = hl ? Ql : Qh;
      *(uint4*)&dst[r * WB + k4] = src[(t0 + r) * 8 + (k4 >> 2)];
    }
    __syncthreads();
    if (tid < 64) {
      const __nv_bfloat16* qh = (const __nv_bfloat16*)Qh + tid * 2 * WB;
      const __nv_bfloat16* ql = (const __nv_bfloat16*)Ql + tid * 2 * WB;
      const float* el = Er + (size_t)(TT - 1) * HH;
      float acc = 0.f;
#pragma unroll
      for (int h = 0; h < HH; h++)
        acc += (__bfloat162float(qh[h]) + __bfloat162float(ql[h])) * el[h];
      ds[tid] = acc;
    }
    // Pre-fill iteration 0: K, Qr, Vt(buf 0), Er (96 rows). All threads.
    {
      int rbase0 = t0 - 33;
      for (int i = tid; i < 3072; i += 256) {
        if (i < 1536) {
          int seg = i >> 9, rem = i & 511;
          int hl = rem >> 8, rem2 = rem & 255;
          if (seg == 0) {
            int r = rem2 >> 3, k4 = (rem2 & 7) << 2;
            uint4 val = (hl ? KL4 : KH4)[r * 8 + (k4 >> 2)];
            uint32_t* dst = hl ? Kl : Kh;
            *(uint4*)&dst[r * WB + k4] = val;
          } else if (seg == 1) {
            int r = rem2 >> 3, k4 = (rem2 & 7) << 2;
            uint4 val = (hl ? QL4 : QH4)[(1 + r) * 8 + (k4 >> 2)];
            uint32_t* dst = hl ? Qrl : Qrh;
            *(uint4*)&dst[r * WB + k4] = val;
          } else {
            int h = rem2 >> 2, t4 = (rem2 & 3) << 2;
            uint4 val = (hl ? VTL4 : VTH4)[h * 256 + (t4 >> 2)];
            uint32_t* dst = hl ? Vtl : Vth;
            *(uint4*)&dst[h * WP + t4] = val;
          }
        } else {
          int idx = i - 1536;
          int xr = idx >> 4, sub = idx & 15;
          int hl = sub >> 3, k4 = (sub & 7) << 2;
          int r = rbase0 + xr;
          int slot = (r + 2112) % 96;
          int rc = r < 0 ? 0 : r;
          uint4 val = (hl ? EL4 : EH4)[rc * 8 + (k4 >> 2)];
          uint32_t* dst = hl ? Erl : Erh;
          *(uint4*)&dst[slot * WB + k4] = val;
        }
      }
    }

    float O[8][4] = {};
    float m_a = -1e30f, m_b = -1e30f, l_a = 0.f, l_b = 0.f;
    int niter = t0 / 32 + 2;

    for (int it = 0; it < niter; it++) {
      int s0 = it * 32;
      int rbase = t0 - s0 - 33;
      int p = it & 1;
      __syncthreads();  // A: fills visible

      float sf[4][4] = {};
      if (sWarp) {
        // S = Q @ K^T (16 rows x 32 cols, k64)
#pragma unroll
        for (int c4 = 0; c4 < 4; c4++) {
          uint32_t kof = 32 * c4;
          uint32_t ah[4], al[4], bh[8], bl[8];
          ldm4(ah[0], ah[1], ah[2], ah[3], aQh + kof);
          ldm4(al[0], al[1], al[2], al[3], aQl + kof);
          ldm4(bh[0], bh[1], bh[2], bh[3], bKh + kof);
          ldm4(bh[4], bh[5], bh[6], bh[7], bKh + 16 * WB * 4 + kof);
          ldm4(bl[0], bl[1], bl[2], bl[3], bKl + kof);
          ldm4(bl[4], bl[5], bl[6], bl[7], bKl + 16 * WB * 4 + kof);
#pragma unroll
          for (int u = 0; u < 4; u++)
            mmax2(sf[u], ah, al, bh[2 * u], bh[2 * u + 1], bl[2 * u],
                  bl[2 * u + 1]);
        }
      } else {
        // G[j][slot] = Qr[j].Ers[slot] (16 rows x 48 slots, k64)
        float gf[6][4] = {};
#pragma unroll
        for (int c4 = 0; c4 < 4; c4++) {
          uint32_t kof = 32 * c4;
          uint32_t ah[4], al[4], bh[12], bl[12];
          ldm4(ah[0], ah[1], ah[2], ah[3], aRh + kof);
          ldm4(al[0], al[1], al[2], al[3], aRl + kof);
          ldm4(bh[0], bh[1], bh[2], bh[3], bEh + kof);
          ldm4(bh[4], bh[5], bh[6], bh[7], bEh + 16 * WB * 4 + kof);
          ldm4(bh[8], bh[9], bh[10], bh[11], bEh + 32 * WB * 4 + kof);
          ldm4(bl[0], bl[1], bl[2], bl[3], bEl + kof);
          ldm4(bl[4], bl[5], bl[6], bl[7], bEl + 16 * WB * 4 + kof);
          ldm4(bl[8], bl[9], bl[10], bl[11], bEl + 32 * WB * 4 + kof);
#pragma unroll
          for (int v = 0; v < 6; v++)
            mmax2(gf[v], ah, al, bh[2 * v], bh[2 * v + 1], bl[2 * v],
                  bl[2 * v + 1]);
        }
        int r1 = 16 * mt2 + g, r2 = r1 + 8;
#pragma unroll
        for (int v = 0; v < 6; v++) {
          int n0 = 48 * cg + 8 * v + 2 * tg;
          *(float2*)&Gs[r1 * PG + n0] = make_float2(gf[v][0], gf[v][1]);
          *(float2*)&Gs[r2 * PG + n0] = make_float2(gf[v][2], gf[v][3]);
        }
      }
      __syncthreads();  // B: Gs ready; S done with K; G done with Qr/Er

      if (sWarp) {
        // --- register softmax ---
        int ra = 16 * ws + g, rb = ra + 8;
        int ta = t0 + ra, tb = t0 + rb;
        int baseA = rbase + ra + 31 + 2112;
        int baseB = rbase + rb + 31 + 2112;
        float va[8], vb[8];
        float dsa = ds[ra], dsb = ds[rb];
#pragma unroll
        for (int u = 0; u < 4; u++) {
#pragma unroll
          for (int e = 0; e < 2; e++) {
            int j = 8 * u + 2 * tg + e;
            int s = s0 + j;
            float adda = 0.f, addb = 0.f;
            if (s <= ta - 2)
              adda = Gs[j * PG + (baseA - j) % 96];
            else if (s == ta)
              adda = dsa;
            if (s <= tb - 2)
              addb = Gs[j * PG + (baseB - j) % 96];
            else if (s == tb)
              addb = dsb;
            float xa = SCALE * sf[u][e] + adda;
            float xb = SCALE * sf[u][2 + e] + addb;
            if (s > ta) xa = -1e30f;
            if (s > tb) xb = -1e30f;
            va[2 * u + e] = xa;
            vb[2 * u + e] = xb;
          }
        }
        float ma = va[0], mb = vb[0];
#pragma unroll
        for (int i = 1; i < 8; i++) {
          ma = fmaxf(ma, va[i]);
          mb = fmaxf(mb, vb[i]);
        }
        ma = fmaxf(ma, __shfl_xor_sync(0xffffffffu, ma, 1));
        ma = fmaxf(ma, __shfl_xor_sync(0xffffffffu, ma, 2));
        mb = fmaxf(mb, __shfl_xor_sync(0xffffffffu, mb, 1));
        mb = fmaxf(mb, __shfl_xor_sync(0xffffffffu, mb, 2));
        float mna = fmaxf(m_a, ma), mnb = fmaxf(m_b, mb);
        float ala = __expf(m_a - mna), alb = __expf(m_b - mnb);
        m_a = mna;
        m_b = mnb;
        float pa[8], pb[8];
        float rsa = 0.f, rsb = 0.f;
#pragma unroll
        for (int i = 0; i < 8; i++) {
          pa[i] = __expf(va[i] - mna);
          pb[i] = __expf(vb[i] - mnb);
          rsa += pa[i];
          rsb += pb[i];
        }
        rsa += __shfl_xor_sync(0xffffffffu, rsa, 1);
        rsa += __shfl_xor_sync(0xffffffffu, rsa, 2);
        rsb += __shfl_xor_sync(0xffffffffu, rsb, 1);
        rsb += __shfl_xor_sync(0xffffffffu, rsb, 2);
        l_a = ala * l_a + rsa;
        l_b = alb * l_b + rsb;
        // pack P into A fragments: chunk c2 uses pa[4c2..4c2+3], pb[...]
        uint32_t pah[2][4], pal[2][4];
#pragma unroll
        for (int c2 = 0; c2 < 2; c2++) {
          pk(pa[4 * c2 + 0], pa[4 * c2 + 1], pah[c2][0], pal[c2][0]);
          pk(pb[4 * c2 + 0], pb[4 * c2 + 1], pah[c2][1], pal[c2][1]);
          pk(pa[4 * c2 + 2], pa[4 * c2 + 3], pah[c2][2], pal[c2][2]);
          pk(pb[4 * c2 + 2], pb[4 * c2 + 3], pah[c2][3], pal[c2][3]);
        }
        // scale O and accumulate AV (16 rows x 64 cols)
#pragma unroll
        for (int v = 0; v < 8; v++) {
          O[v][0] *= ala;
          O[v][1] *= ala;
          O[v][2] *= alb;
          O[v][3] *= alb;
        }
        uint32_t vbh = bVh0 + (uint32_t)(p * VT_BUF * 4);
        uint32_t vbl = bVl0 + (uint32_t)(p * VT_BUF * 4);
#pragma unroll
        for (int c2 = 0; c2 < 2; c2++) {
          uint32_t kof = 32 * c2;
#pragma unroll
          for (int nt = 0; nt < 4; nt++) {
            uint32_t bh[4], bl[4];
            ldm4(bh[0], bh[1], bh[2], bh[3], vbh + nt * 16 * WP * 4 + kof);
            ldm4(bl[0], bl[1], bl[2], bl[3], vbl + nt * 16 * WP * 4 + kof);
            mmax2(O[2 * nt], pah[c2], pal[c2], bh[0], bh[1], bl[0], bl[1]);
            mmax2(O[2 * nt + 1], pah[c2], pal[c2], bh[2], bh[3], bl[2],
                  bl[3]);
          }
        }
      } else if (it + 1 < niter) {
        // --- producer: prefetch tiles for it+1 ---
        int s0n = s0 + 32;
        int rbn = rbase - 32;
        int q = (it + 1) & 1;
        int ft = tid & 127;
        for (int i = ft; i < 2048; i += 128) {
          int seg = i >> 9, rem = i & 511;
          int hl = rem >> 8, rem2 = rem & 255;
          if (seg == 0) {
            int r = rem2 >> 3, k4 = (rem2 & 7) << 2;
            uint4 val = (hl ? KL4 : KH4)[(s0n + r) * 8 + (k4 >> 2)];
            uint32_t* dst = hl ? Kl : Kh;
            *(uint4*)&dst[r * WB + k4] = val;
          } else if (seg == 1) {
            int r = rem2 >> 3, k4 = (rem2 & 7) << 2;
            int rq = s0n + 1 + r;
            if (rq > TT - 1) rq = TT - 1;  // clamped rows feed masked slots
            uint4 val = (hl ? QL4 : QH4)[rq * 8 + (k4 >> 2)];
            uint32_t* dst = hl ? Qrl : Qrh;
            *(uint4*)&dst[r * WB + k4] = val;
          } else if (seg == 2) {
            int h = rem2 >> 2, t4 = (rem2 & 3) << 2;
            uint4 val = (hl ? VTL4 : VTH4)[h * 256 + (s0n >> 3) + (t4 >> 2)];
            uint32_t* dst = hl ? Vtl : Vth;
            *(uint4*)&dst[q * VT_BUF + h * WP + t4] = val;
          } else {
            int xr = rem2 >> 3, k4 = (rem2 & 7) << 2;
            int r = rbn + xr;
            int slot = (r + 2112) % 96;
            int rc = r < 0 ? 0 : r;
            uint4 val = (hl ? EL4 : EH4)[rc * 8 + (k4 >> 2)];
            uint32_t* dst = hl ? Erl : Erh;
            *(uint4*)&dst[slot * WB + k4] = val;
          }
        }
      }
    }

    // output: each S warp writes its own 16 rows x 64 cols
    if (sWarp) {
      int ra = 16 * ws + g, rb = ra + 8;
      float inv1 = 1.f / l_a, inv2 = 1.f / l_b;
#pragma unroll
      for (int v = 0; v < 8; v++) {
        int nc = 8 * v + 2 * tg;
        *(float2*)&out[((size_t)b * TT + t0 + ra) * HH + nc] =
            make_float2(O[v][0] * inv1, O[v][1] * inv1);
        *(float2*)&out[((size_t)b * TT + t0 + rb) * HH + nc] =
            make_float2(O[v][2] * inv2, O[v][3] * inv2);
      }
    }
  }
}

extern "C" void kernel_launch(void* const* d_in, const int* in_sizes, int n_in,
                              void* d_out, int out_size) {
  (void)in_sizes;
  (void)n_in;
  (void)out_size;
  const float* x = (const float*)d_in[0];
  const float* Wq = (const float*)d_in[1];
  const float* Wk = (const float*)d_in[2];
  const float* Wv = (const float*)d_in[3];
  const float* Er = (const float*)d_in[4];
  float* out = (float*)d_out;

  cudaFuncSetAttribute(qkv_mma, cudaFuncAttributeMaxDynamicSharedMemorySize,
                       QKV_WORDS * 4);
  cudaFuncSetAttribute(attn_mma, cudaFuncAttributeMaxDynamicSharedMemorySize,
                       ATTN_WORDS * 4);

  prep_w<<<dim3(192 * 512 / 256), 256>>>(Wq, Wk, Wv);
  prep_er<<<dim3(TT * HH / 256), 256>>>(Er);
  qkv_mma<<<dim3((BB * TT) / 64), 256, QKV_WORDS * 4>>>(x);
  attn_mma<<<dim3(TT / 128, BB), 256, ATTN_WORDS * 4>>>(Er, out);
}

// round 15
// speedup vs baseline: 1.3962x; 1.3962x over previous
#include <cuda_runtime.h>
#include <cuda_bf16.h>
#include <cstdint>

#define BB 16
#define TT 2048
#define CC 512
#define HH 64
#define SCALE 0.125f

// Q,K split bf16 (packed pairs), row-major [b*T + t][64]
__device__ __nv_bfloat16 g_qh[BB * TT * HH];
__device__ __nv_bfloat16 g_ql[BB * TT * HH];
__device__ __nv_bfloat16 g_kh[BB * TT * HH];
__device__ __nv_bfloat16 g_kl[BB * TT * HH];
// V split + transposed: [b*64 + h][t]
__device__ __nv_bfloat16 g_vth[BB * HH * TT];
__device__ __nv_bfloat16 g_vtl[BB * HH * TT];
// Er split: [r][64]
__device__ __nv_bfloat16 g_erh[TT * HH];
__device__ __nv_bfloat16 g_erl[TT * HH];
// W transposed+split: [n (0..191)][k (0..511)]
__device__ __nv_bfloat16 g_wth[192 * 512];
__device__ __nv_bfloat16 g_wtl[192 * 512];

__device__ __forceinline__ void pk(float x, float y, uint32_t& h, uint32_t& l) {
  __nv_bfloat16 hx = __float2bfloat16(x), hy = __float2bfloat16(y);
  float rx = x - __bfloat162float(hx), ry = y - __bfloat162float(hy);
  __nv_bfloat16 lx = __float2bfloat16(rx), ly = __float2bfloat16(ry);
  h = (uint32_t)__bfloat16_as_ushort(hx) |
      ((uint32_t)__bfloat16_as_ushort(hy) << 16);
  l = (uint32_t)__bfloat16_as_ushort(lx) |
      ((uint32_t)__bfloat16_as_ushort(ly) << 16);
}
__device__ __forceinline__ void pk1(float x, __nv_bfloat16& h,
                                    __nv_bfloat16& l) {
  h = __float2bfloat16(x);
  l = __float2bfloat16(x - __bfloat162float(h));
}

__device__ __forceinline__ void mma16(float* c, uint32_t a0, uint32_t a1,
                                      uint32_t a2, uint32_t a3, uint32_t b0,
                                      uint32_t b1) {
  asm volatile(
      "mma.sync.aligned.m16n8k16.row.col.f32.bf16.bf16.f32 "
      "{%0,%1,%2,%3}, {%4,%5,%6,%7}, {%8,%9}, {%0,%1,%2,%3};"
      : "+f"(c[0]), "+f"(c[1]), "+f"(c[2]), "+f"(c[3])
      : "r"(a0), "r"(a1), "r"(a2), "r"(a3), "r"(b0), "r"(b1));
}
__device__ __forceinline__ void mmax2(float* c, const uint32_t* ah,
                                      const uint32_t* al, uint32_t bh0,
                                      uint32_t bh1, uint32_t bl0,
                                      uint32_t bl1) {
  mma16(c, ah[0], ah[1], ah[2], ah[3], bl0, bl1);
  mma16(c, al[0], al[1], al[2], al[3], bh0, bh1);
  mma16(c, ah[0], ah[1], ah[2], ah[3], bh0, bh1);
}

__device__ __forceinline__ void ldm4(uint32_t& r0, uint32_t& r1, uint32_t& r2,
                                     uint32_t& r3, uint32_t addr) {
  asm volatile(
      "ldmatrix.sync.aligned.m8n8.x4.shared.b16 {%0,%1,%2,%3}, [%4];"
      : "=r"(r0), "=r"(r1), "=r"(r2), "=r"(r3)
      : "r"(addr));
}
__device__ __forceinline__ uint32_t sptr(const void* p) {
  return (uint32_t)__cvta_generic_to_shared(p);
}
__device__ __forceinline__ void cpa16(uint32_t saddr, const void* gaddr) {
  asm volatile("cp.async.cg.shared.global [%0], [%1], 16;\n" ::"r"(saddr),
               "l"(gaddr));
}
#define CP_COMMIT() asm volatile("cp.async.commit_group;\n" ::: "memory")
#define CP_WAIT0() asm volatile("cp.async.wait_group 0;\n" ::: "memory")

// ---------------------------------------------------------------------------
// One-shot preps
// ---------------------------------------------------------------------------
__global__ __launch_bounds__(256) void prep_w(const float* __restrict__ Wq,
                                              const float* __restrict__ Wk,
                                              const float* __restrict__ Wv) {
  int idx = blockIdx.x * 256 + threadIdx.x;
  int n = idx >> 9, k = idx & 511;
  const float* Wm = n < 64 ? Wq : (n < 128 ? Wk : Wv);
  float v = Wm[(size_t)k * HH + (n & 63)];
  __nv_bfloat16 h, l;
  pk1(v, h, l);
  g_wth[idx] = h;
  g_wtl[idx] = l;
}

__global__ __launch_bounds__(256) void prep_er(const float* __restrict__ Er) {
  int idx = blockIdx.x * 256 + threadIdx.x;
  __nv_bfloat16 h, l;
  pk1(Er[idx], h, l);
  g_erh[idx] = h;
  g_erl[idx] = l;
}

// ---------------------------------------------------------------------------
// QKV projection (unchanged).
// ---------------------------------------------------------------------------
#define WX 36
#define WW 36
#define QKV_WORDS (2 * 64 * WX + 2 * 192 * WW)
__global__ __launch_bounds__(256) void qkv_mma(const float* __restrict__ x) {
  extern __shared__ uint32_t qsm[];
  uint32_t* Xh = qsm;
  uint32_t* Xl = Xh + 64 * WX;
  uint32_t* WTh = Xl + 64 * WX;
  uint32_t* WTl = WTh + 192 * WW;
  int tid = threadIdx.x, w = tid >> 5, lane = tid & 31;
  int g = lane >> 2, tg = lane & 3;
  int row0 = blockIdx.x * 64;
  int mt = w & 3, nh = w >> 2;
  float acc[12][4] = {};

  for (int k0 = 0; k0 < CC; k0 += 64) {
    __syncthreads();
    for (int i = tid; i < 1024; i += 256) {
      int r = i >> 4, h4 = (i & 15) << 2;
      float4 v4 = *(const float4*)&x[(size_t)(row0 + r) * CC + k0 + h4];
      uint32_t h01, l01, h23, l23;
      pk(v4.x, v4.y, h01, l01);
      pk(v4.z, v4.w, h23, l23);
      int wc = r * WX + (h4 >> 1);
      *(uint2*)&Xh[wc] = make_uint2(h01, h23);
      *(uint2*)&Xl[wc] = make_uint2(l01, l23);
    }
    for (int i = tid; i < 1536; i += 256) {
      int n = i >> 3, w4 = (i & 7) << 2;
      int src = n * 256 + (k0 >> 1) + w4;
      *(uint4*)&WTh[n * WW + w4] = *(const uint4*)((const uint32_t*)g_wth + src);
      *(uint4*)&WTl[n * WW + w4] = *(const uint4*)((const uint32_t*)g_wtl + src);
    }
    __syncthreads();
    int r1 = 16 * mt + g, r2 = r1 + 8;
#pragma unroll
    for (int c4 = 0; c4 < 4; c4++) {
      int kw = 8 * c4;
      uint32_t ah[4], al[4];
      ah[0] = Xh[r1 * WX + kw + tg];
      ah[1] = Xh[r2 * WX + kw + tg];
      ah[2] = Xh[r1 * WX + kw + 4 + tg];
      ah[3] = Xh[r2 * WX + kw + 4 + tg];
      al[0] = Xl[r1 * WX + kw + tg];
      al[1] = Xl[r2 * WX + kw + tg];
      al[2] = Xl[r1 * WX + kw + 4 + tg];
      al[3] = Xl[r2 * WX + kw + 4 + tg];
#pragma unroll
      for (int v = 0; v < 12; v++) {
        int n = 8 * (12 * nh + v) + g;
        uint32_t bh0 = WTh[n * WW + kw + tg];
        uint32_t bh1 = WTh[n * WW + kw + 4 + tg];
        uint32_t bl0 = WTl[n * WW + kw + tg];
        uint32_t bl1 = WTl[n * WW + kw + 4 + tg];
        mmax2(acc[v], ah, al, bh0, bh1, bl0, bl1);
      }
    }
  }
  int r0g = row0 + 16 * mt + g;
#pragma unroll
  for (int v = 0; v < 12; v++) {
    int ncol = 8 * (12 * nh + v) + 2 * tg;
    int m = ncol >> 6, nn = ncol & 63;
    if (m < 2) {
      uint32_t* oh = (uint32_t*)(m == 0 ? g_qh : g_kh);
      uint32_t* ol = (uint32_t*)(m == 0 ? g_ql : g_kl);
      uint32_t h, l;
      pk(acc[v][0], acc[v][1], h, l);
      oh[(size_t)r0g * 32 + (nn >> 1)] = h;
      ol[(size_t)r0g * 32 + (nn >> 1)] = l;
      pk(acc[v][2], acc[v][3], h, l);
      oh[(size_t)(r0g + 8) * 32 + (nn >> 1)] = h;
      ol[(size_t)(r0g + 8) * 32 + (nn >> 1)] = l;
    } else {
      int bidx = r0g >> 11, t = r0g & 2047;
      size_t base = ((size_t)bidx * HH + nn) * TT + t;
      __nv_bfloat16 h, l;
      pk1(acc[v][0], h, l);
      g_vth[base] = h;
      g_vtl[base] = l;
      pk1(acc[v][1], h, l);
      g_vth[base + TT] = h;
      g_vtl[base + TT] = l;
      pk1(acc[v][2], h, l);
      g_vth[base + 8] = h;
      g_vtl[base + 8] = l;
      pk1(acc[v][3], h, l);
      g_vth[base + TT + 8] = h;
      g_vtl[base + TT + 8] = l;
    }
  }
}

// ---------------------------------------------------------------------------
// Fused attention: round-12 compute structure + cp.async prefetch pipeline.
//   3 barriers/iter. Vt double-buffered; K/Qr/Er prefetched into dead buffers.
// ---------------------------------------------------------------------------
#define WB 36
#define WP 20
#define PG 104
#define VT (64 * WP)
#define ATTN_WORDS                                                     \
  (2 * 64 * WB + 4 * 32 * WB + 2 * 96 * WB + 4 * VT + 2 * 64 * WP + \
   32 * PG + 3 * 64)

__global__ __launch_bounds__(256, 2) void attn_mma(
    const float* __restrict__ Er, float* __restrict__ out) {
  extern __shared__ uint32_t sm[];
  uint32_t* Qh = sm;
  uint32_t* Ql = Qh + 64 * WB;
  uint32_t* Kh = Ql + 64 * WB;
  uint32_t* Kl = Kh + 32 * WB;
  uint32_t* Qrh = Kl + 32 * WB;
  uint32_t* Qrl = Qrh + 32 * WB;
  uint32_t* Erh = Qrl + 32 * WB;
  uint32_t* Erl = Erh + 96 * WB;
  uint32_t* Vth = Erl + 96 * WB;     // [2][64][WP]
  uint32_t* Vtl = Vth + 2 * VT;      // [2][64][WP]
  uint32_t* Ph = Vtl + 2 * VT;
  uint32_t* Pl = Ph + 64 * WP;
  float* Gs = (float*)(Pl + 64 * WP);  // 32 x PG
  float* ds = Gs + 32 * PG;
  float* as_ = ds + 64;
  float* lsm = as_ + 64;

  int tid = threadIdx.x, w = tid >> 5, lane = tid & 31;
  int g = lane >> 2, tg = lane & 3;
  int b = blockIdx.y;
  const uint4* QH4 = (const uint4*)g_qh + (size_t)b * TT * 8;
  const uint4* QL4 = (const uint4*)g_ql + (size_t)b * TT * 8;
  const uint4* KH4 = (const uint4*)g_kh + (size_t)b * TT * 8;
  const uint4* KL4 = (const uint4*)g_kl + (size_t)b * TT * 8;
  const uint4* VTH4 = (const uint4*)g_vth + (size_t)b * HH * 256;
  const uint4* VTL4 = (const uint4*)g_vtl + (size_t)b * HH * 256;
  const uint4* EH4 = (const uint4*)g_erh;
  const uint4* EL4 = (const uint4*)g_erl;

  uint32_t spKh = sptr(Kh), spKl = sptr(Kl);
  uint32_t spQrh = sptr(Qrh), spQrl = sptr(Qrl);
  uint32_t spErh = sptr(Erh), spErl = sptr(Erl);
  uint32_t spVth = sptr(Vth), spVtl = sptr(Vtl);

  int smt = w & 3, snh = w >> 2;

  // ldmatrix lane-address components (byte offsets)
  int lrowA = lane & 15;
  int lcolA = ((lane >> 4) << 2);
  int lrowB = (lane & 7) + ((lane >> 4) << 3);
  int lcolB = ((lane >> 3) & 1) << 2;
  uint32_t aQh = sptr(Qh) + ((16 * w + lrowA) * WB + lcolA) * 4;
  uint32_t aQl = aQh + (uint32_t)(64 * WB * 4);
  uint32_t bKh = spKh + (lrowB * WB + lcolB) * 4;
  uint32_t bKl = bKh + (uint32_t)(32 * WB * 4);
  int gw = w - 4, mt2 = gw & 1, cg = gw >> 1;
  uint32_t aRh = spQrh + ((16 * mt2 + lrowA) * WB + lcolA) * 4;
  uint32_t aRl = aRh + (uint32_t)(32 * WB * 4);
  uint32_t bEh = spErh + ((48 * cg + lrowB) * WB + lcolB) * 4;
  uint32_t bEl = bEh + (uint32_t)(96 * WB * 4);
  uint32_t aPh = sptr(Ph) + ((16 * smt + lrowA) * WP + lcolA) * 4;
  uint32_t aPl = aPh + (uint32_t)(64 * WP * 4);
  uint32_t bVh0 = spVth + ((32 * snh + lrowB) * WP + lcolB) * 4;

  for (int half = 0; half < 2; half++) {
    int t0 = half == 0 ? blockIdx.x * 64 : (TT - 64 - blockIdx.x * 64);
    __syncthreads();
    for (int i = tid; i < 1024; i += 256) {  // Q tile
      int hl = i >> 9, rem = i & 511;
      int r = rem >> 3, k4 = (rem & 7) << 2;
      const uint4* src = hl ? QL4 : QH4;
      uint32_t* dst = hl ? Ql : Qh;
      *(uint4*)&dst[r * WB + k4] = src[(t0 + r) * 8 + (k4 >> 2)];
    }
    // Initial prefetch: K(s0=0), Qr, Vt buf0, Er 96 rows — cp.async
    {
      int rbase0 = t0 - 33;
      for (int i = tid; i < 3072; i += 256) {
        if (i < 1536) {
          int seg = i >> 9, rem = i & 511;
          int hl = rem >> 8, rem2 = rem & 255;
          if (seg == 0) {
            int r = rem2 >> 3, k4 = (rem2 & 7) << 2;
            cpa16((hl ? spKl : spKh) + (r * WB + k4) * 4,
                  (hl ? KL4 : KH4) + r * 8 + (k4 >> 2));
          } else if (seg == 1) {
            int r = rem2 >> 3, k4 = (rem2 & 7) << 2;
            cpa16((hl ? spQrl : spQrh) + (r * WB + k4) * 4,
                  (hl ? QL4 : QH4) + (1 + r) * 8 + (k4 >> 2));
          } else {
            int h = rem2 >> 2, t4 = (rem2 & 3) << 2;
            cpa16((hl ? spVtl : spVth) + (h * WP + t4) * 4,
                  (hl ? VTL4 : VTH4) + h * 256 + (t4 >> 2));
          }
        } else {
          int idx = i - 1536;
          int xr = idx >> 4, sub = idx & 15;
          int hl = sub >> 3, k4 = (sub & 7) << 2;
          int r = rbase0 + xr;
          int slot = (r + 2112) % 96;
          int rc = r < 0 ? 0 : r;
          cpa16((hl ? spErl : spErh) + (slot * WB + k4) * 4,
                (hl ? EL4 : EH4) + rc * 8 + (k4 >> 2));
        }
      }
      CP_COMMIT();
    }
    __syncthreads();  // Q visible for ds
    if (tid < 64) {
      const __nv_bfloat16* qh = (const __nv_bfloat16*)Qh + tid * 2 * WB;
      const __nv_bfloat16* ql = (const __nv_bfloat16*)Ql + tid * 2 * WB;
      const float* el = Er + (size_t)(TT - 1) * HH;
      float acc = 0.f;
#pragma unroll
      for (int h = 0; h < HH; h++)
        acc += (__bfloat162float(qh[h]) + __bfloat162float(ql[h])) * el[h];
      ds[tid] = acc;
    }

    float O[4][4] = {};
    float m_a = -1e30f, m_b = -1e30f, l_a = 0.f, l_b = 0.f;
    int niter = t0 / 32 + 2;

    for (int it = 0; it < niter; it++) {
      int s0 = it * 32;
      int rbase = t0 - s0 - 33;
      int p = it & 1;
      CP_WAIT0();
      __syncthreads();  // A: tiles (and ds on it=0) visible

      float sf[4][4] = {};  // S fragments (warps 0-3)
      if (w < 4) {
#pragma unroll
        for (int c4 = 0; c4 < 4; c4++) {
          uint32_t kof = 32 * c4;
          uint32_t ah[4], al[4], bh[8], bl[8];
          ldm4(ah[0], ah[1], ah[2], ah[3], aQh + kof);
          ldm4(al[0], al[1], al[2], al[3], aQl + kof);
          ldm4(bh[0], bh[1], bh[2], bh[3], bKh + kof);
          ldm4(bh[4], bh[5], bh[6], bh[7], bKh + 16 * WB * 4 + kof);
          ldm4(bl[0], bl[1], bl[2], bl[3], bKl + kof);
          ldm4(bl[4], bl[5], bl[6], bl[7], bKl + 16 * WB * 4 + kof);
#pragma unroll
          for (int u = 0; u < 4; u++)
            mmax2(sf[u], ah, al, bh[2 * u], bh[2 * u + 1], bl[2 * u],
                  bl[2 * u + 1]);
        }
      } else {
        float gf[6][4] = {};
#pragma unroll
        for (int c4 = 0; c4 < 4; c4++) {
          uint32_t kof = 32 * c4;
          uint32_t ah[4], al[4], bh[12], bl[12];
          ldm4(ah[0], ah[1], ah[2], ah[3], aRh + kof);
          ldm4(al[0], al[1], al[2], al[3], aRl + kof);
          ldm4(bh[0], bh[1], bh[2], bh[3], bEh + kof);
          ldm4(bh[4], bh[5], bh[6], bh[7], bEh + 16 * WB * 4 + kof);
          ldm4(bh[8], bh[9], bh[10], bh[11], bEh + 32 * WB * 4 + kof);
          ldm4(bl[0], bl[1], bl[2], bl[3], bEl + kof);
          ldm4(bl[4], bl[5], bl[6], bl[7], bEl + 16 * WB * 4 + kof);
          ldm4(bl[8], bl[9], bl[10], bl[11], bEl + 32 * WB * 4 + kof);
#pragma unroll
          for (int v = 0; v < 6; v++)
            mmax2(gf[v], ah, al, bh[2 * v], bh[2 * v + 1], bl[2 * v],
                  bl[2 * v + 1]);
        }
        int r1 = 16 * mt2 + g, r2 = r1 + 8;
#pragma unroll
        for (int v = 0; v < 6; v++) {
          int n0 = 48 * cg + 8 * v + 2 * tg;
          *(float2*)&Gs[r1 * PG + n0] = make_float2(gf[v][0], gf[v][1]);
          *(float2*)&Gs[r2 * PG + n0] = make_float2(gf[v][2], gf[v][3]);
        }
      }
      __syncthreads();  // B: Gs ready; K/Qr/Er buffers now dead

      // Prefetch next iteration's tiles into the dead buffers (all threads)
      if (it + 1 < niter) {
        int s0n = s0 + 32;
        int rbn = rbase - 32;
        int q = (it + 1) & 1;
#pragma unroll
        for (int ii = 0; ii < 8; ii++) {
          int i = tid + 256 * ii;
          int seg = i >> 9, rem = i & 511;
          int hl = rem >> 8, rem2 = rem & 255;
          if (seg == 0) {
            int r = rem2 >> 3, k4 = (rem2 & 7) << 2;
            cpa16((hl ? spKl : spKh) + (r * WB + k4) * 4,
                  (hl ? KL4 : KH4) + (s0n + r) * 8 + (k4 >> 2));
          } else if (seg == 1) {
            int r = rem2 >> 3, k4 = (rem2 & 7) << 2;
            int rq = s0n + 1 + r;
            if (rq > TT - 1) rq = TT - 1;  // clamped rows feed masked slots
            cpa16((hl ? spQrl : spQrh) + (r * WB + k4) * 4,
                  (hl ? QL4 : QH4) + rq * 8 + (k4 >> 2));
          } else if (seg == 2) {
            int h = rem2 >> 2, t4 = (rem2 & 3) << 2;
            cpa16((hl ? spVtl : spVth) + (q * VT + h * WP + t4) * 4,
                  (hl ? VTL4 : VTH4) + h * 256 + (s0n >> 3) + (t4 >> 2));
          } else {
            int xr = rem2 >> 3, k4 = (rem2 & 7) << 2;
            int r = rbn + xr;
            int slot = (r + 2112) % 96;
            int rc = r < 0 ? 0 : r;
            cpa16((hl ? spErl : spErh) + (slot * WB + k4) * 4,
                  (hl ? EL4 : EH4) + rc * 8 + (k4 >> 2));
          }
        }
        CP_COMMIT();
      }

      if (w < 4) {
        // in-register softmax for rows ra, rb
        int ra = 16 * w + g, rb = ra + 8;
        int ta = t0 + ra, tb = t0 + rb;
        int bmA = (rbase + ra + 31 + 2112) % 96;
        int bmB = (rbase + rb + 31 + 2112) % 96;
        float va[8], vb[8];
        float dsa = ds[ra], dsb = ds[rb];
#pragma unroll
        for (int u = 0; u < 4; u++) {
#pragma unroll
          for (int e = 0; e < 2; e++) {
            int j = 8 * u + 2 * tg + e;
            int s = s0 + j;
            int sA = bmA - j;
            sA += (sA < 0) ? 96 : 0;
            int sB = bmB - j;
            sB += (sB < 0) ? 96 : 0;
            float adda = 0.f, addb = 0.f;
            if (s <= ta - 2)
              adda = Gs[j * PG + sA];
            else if (s == ta)
              adda = dsa;
            if (s <= tb - 2)
              addb = Gs[j * PG + sB];
            else if (s == tb)
              addb = dsb;
            float xa = SCALE * sf[u][e] + adda;
            float xb = SCALE * sf[u][2 + e] + addb;
            if (s > ta) xa = -1e30f;
            if (s > tb) xb = -1e30f;
            va[2 * u + e] = xa;
            vb[2 * u + e] = xb;
          }
        }
        float ma = va[0], mb = vb[0];
#pragma unroll
        for (int i = 1; i < 8; i++) {
          ma = fmaxf(ma, va[i]);
          mb = fmaxf(mb, vb[i]);
        }
        ma = fmaxf(ma, __shfl_xor_sync(0xffffffffu, ma, 1));
        ma = fmaxf(ma, __shfl_xor_sync(0xffffffffu, ma, 2));
        mb = fmaxf(mb, __shfl_xor_sync(0xffffffffu, mb, 1));
        mb = fmaxf(mb, __shfl_xor_sync(0xffffffffu, mb, 2));
        float mna = fmaxf(m_a, ma), mnb = fmaxf(m_b, mb);
        float ala = __expf(m_a - mna), alb = __expf(m_b - mnb);
        m_a = mna;
        m_b = mnb;
        float pa[8], pb[8];
        float rsa = 0.f, rsb = 0.f;
#pragma unroll
        for (int i = 0; i < 8; i++) {
          pa[i] = __expf(va[i] - mna);
          pb[i] = __expf(vb[i] - mnb);
          rsa += pa[i];
          rsb += pb[i];
        }
        rsa += __shfl_xor_sync(0xffffffffu, rsa, 1);
        rsa += __shfl_xor_sync(0xffffffffu, rsa, 2);
        rsb += __shfl_xor_sync(0xffffffffu, rsb, 1);
        rsb += __shfl_xor_sync(0xffffffffu, rsb, 2);
        l_a = ala * l_a + rsa;
        l_b = alb * l_b + rsb;
#pragma unroll
        for (int u = 0; u < 4; u++) {
          uint32_t h, l;
          pk(pa[2 * u], pa[2 * u + 1], h, l);
          Ph[ra * WP + 4 * u + tg] = h;
          Pl[ra * WP + 4 * u + tg] = l;
          pk(pb[2 * u], pb[2 * u + 1], h, l);
          Ph[rb * WP + 4 * u + tg] = h;
          Pl[rb * WP + 4 * u + tg] = l;
        }
        if (tg == 0) {
          as_[ra] = ala;
          as_[rb] = alb;
        }
      }
      __syncthreads();  // C: P, as_ ready

      // O += P(64x32) @ V(32x64) via Vt buffer p, all warps
      {
        int r1 = 16 * smt + g, r2 = r1 + 8;
        float aa1 = as_[r1], aa2 = as_[r2];
#pragma unroll
        for (int v = 0; v < 4; v++) {
          O[v][0] *= aa1;
          O[v][1] *= aa1;
          O[v][2] *= aa2;
          O[v][3] *= aa2;
        }
        uint32_t vbh = bVh0 + (uint32_t)(p * VT * 4);
        uint32_t vbl = vbh + (uint32_t)(2 * VT * 4);
#pragma unroll
        for (int c2 = 0; c2 < 2; c2++) {
          uint32_t kof = 32 * c2;
          uint32_t ah[4], al[4], bh[8], bl[8];
          ldm4(ah[0], ah[1], ah[2], ah[3], aPh + kof);
          ldm4(al[0], al[1], al[2], al[3], aPl + kof);
          ldm4(bh[0], bh[1], bh[2], bh[3], vbh + kof);
          ldm4(bh[4], bh[5], bh[6], bh[7], vbh + 16 * WP * 4 + kof);
          ldm4(bl[0], bl[1], bl[2], bl[3], vbl + kof);
          ldm4(bl[4], bl[5], bl[6], bl[7], vbl + 16 * WP * 4 + kof);
#pragma unroll
          for (int v = 0; v < 4; v++)
            mmax2(O[v], ah, al, bh[2 * v], bh[2 * v + 1], bl[2 * v],
                  bl[2 * v + 1]);
        }
      }
    }

    if (w < 4 && tg == 0) {
      lsm[16 * w + g] = l_a;
      lsm[16 * w + g + 8] = l_b;
    }
    __syncthreads();
    int r1 = 16 * smt + g, r2 = r1 + 8;
    float inv1 = 1.f / lsm[r1], inv2 = 1.f / lsm[r2];
#pragma unroll
    for (int v = 0; v < 4; v++) {
      int nc = 32 * snh + 8 * v + 2 * tg;
      *(float2*)&out[((size_t)b * TT + t0 + r1) * HH + nc] =
          make_float2(O[v][0] * inv1, O[v][1] * inv1);
      *(float2*)&out[((size_t)b * TT + t0 + r2) * HH + nc] =
          make_float2(O[v][2] * inv2, O[v][3] * inv2);
    }
  }
}

extern "C" void kernel_launch(void* const* d_in, const int* in_sizes, int n_in,
                              void* d_out, int out_size) {
  (void)in_sizes;
  (void)n_in;
  (void)out_size;
  const float* x = (const float*)d_in[0];
  const float* Wq = (const float*)d_in[1];
  const float* Wk = (const float*)d_in[2];
  const float* Wv = (const float*)d_in[3];
  const float* Er = (const float*)d_in[4];
  float* out = (float*)d_out;

  cudaFuncSetAttribute(qkv_mma, cudaFuncAttributeMaxDynamicSharedMemorySize,
                       QKV_WORDS * 4);
  cudaFuncSetAttribute(attn_mma, cudaFuncAttributeMaxDynamicSharedMemorySize,
                       ATTN_WORDS * 4);

  prep_w<<<dim3(192 * 512 / 256), 256>>>(Wq, Wk, Wv);
  prep_er<<<dim3(TT * HH / 256), 256>>>(Er);
  qkv_mma<<<dim3((BB * TT) / 64), 256, QKV_WORDS * 4>>>(x);
  attn_mma<<<dim3(TT / 128, BB), 256, ATTN_WORDS * 4>>>(Er, out);
}

// round 16
// speedup vs baseline: 1.4145x; 1.0131x over previous
#include <cuda_runtime.h>
#include <cuda_bf16.h>
#include <cstdint>

#define BB 16
#define TT 2048
#define CC 512
#define HH 64
#define SCALE 0.125f

// Q,K split bf16 (packed pairs), row-major [b*T + t][64]
__device__ __nv_bfloat16 g_qh[BB * TT * HH];
__device__ __nv_bfloat16 g_ql[BB * TT * HH];
__device__ __nv_bfloat16 g_kh[BB * TT * HH];
__device__ __nv_bfloat16 g_kl[BB * TT * HH];
// V split + transposed: [b*64 + h][t]
__device__ __nv_bfloat16 g_vth[BB * HH * TT];
__device__ __nv_bfloat16 g_vtl[BB * HH * TT];
// Er split: [r][64]
__device__ __nv_bfloat16 g_erh[TT * HH];
__device__ __nv_bfloat16 g_erl[TT * HH];
// W transposed+split: [n (0..191)][k (0..511)]
__device__ __nv_bfloat16 g_wth[192 * 512];
__device__ __nv_bfloat16 g_wtl[192 * 512];

__device__ __forceinline__ void pk(float x, float y, uint32_t& h, uint32_t& l) {
  __nv_bfloat16 hx = __float2bfloat16(x), hy = __float2bfloat16(y);
  float rx = x - __bfloat162float(hx), ry = y - __bfloat162float(hy);
  __nv_bfloat16 lx = __float2bfloat16(rx), ly = __float2bfloat16(ry);
  h = (uint32_t)__bfloat16_as_ushort(hx) |
      ((uint32_t)__bfloat16_as_ushort(hy) << 16);
  l = (uint32_t)__bfloat16_as_ushort(lx) |
      ((uint32_t)__bfloat16_as_ushort(ly) << 16);
}
__device__ __forceinline__ void pk1(float x, __nv_bfloat16& h,
                                    __nv_bfloat16& l) {
  h = __float2bfloat16(x);
  l = __float2bfloat16(x - __bfloat162float(h));
}

__device__ __forceinline__ void mma16(float* c, uint32_t a0, uint32_t a1,
                                      uint32_t a2, uint32_t a3, uint32_t b0,
                                      uint32_t b1) {
  asm volatile(
      "mma.sync.aligned.m16n8k16.row.col.f32.bf16.bf16.f32 "
      "{%0,%1,%2,%3}, {%4,%5,%6,%7}, {%8,%9}, {%0,%1,%2,%3};"
      : "+f"(c[0]), "+f"(c[1]), "+f"(c[2]), "+f"(c[3])
      : "r"(a0), "r"(a1), "r"(a2), "r"(a3), "r"(b0), "r"(b1));
}
__device__ __forceinline__ void mmax2(float* c, const uint32_t* ah,
                                      const uint32_t* al, uint32_t bh0,
                                      uint32_t bh1, uint32_t bl0,
                                      uint32_t bl1) {
  mma16(c, ah[0], ah[1], ah[2], ah[3], bl0, bl1);
  mma16(c, al[0], al[1], al[2], al[3], bh0, bh1);
  mma16(c, ah[0], ah[1], ah[2], ah[3], bh0, bh1);
}

__device__ __forceinline__ void ldm4(uint32_t& r0, uint32_t& r1, uint32_t& r2,
                                     uint32_t& r3, uint32_t addr) {
  asm volatile(
      "ldmatrix.sync.aligned.m8n8.x4.shared.b16 {%0,%1,%2,%3}, [%4];"
      : "=r"(r0), "=r"(r1), "=r"(r2), "=r"(r3)
      : "r"(addr));
}
__device__ __forceinline__ uint32_t sptr(const void* p) {
  return (uint32_t)__cvta_generic_to_shared(p);
}
__device__ __forceinline__ void cpa16(uint32_t saddr, const void* gaddr) {
  asm volatile("cp.async.cg.shared.global [%0], [%1], 16;\n" ::"r"(saddr),
               "l"(gaddr));
}
#define CP_COMMIT() asm volatile("cp.async.commit_group;\n" ::: "memory")
#define CP_WAIT0() asm volatile("cp.async.wait_group 0;\n" ::: "memory")

// ---------------------------------------------------------------------------
// One-shot preps
// ---------------------------------------------------------------------------
__global__ __launch_bounds__(256) void prep_w(const float* __restrict__ Wq,
                                              const float* __restrict__ Wk,
                                              const float* __restrict__ Wv) {
  int idx = blockIdx.x * 256 + threadIdx.x;
  int n = idx >> 9, k = idx & 511;
  const float* Wm = n < 64 ? Wq : (n < 128 ? Wk : Wv);
  float v = Wm[(size_t)k * HH + (n & 63)];
  __nv_bfloat16 h, l;
  pk1(v, h, l);
  g_wth[idx] = h;
  g_wtl[idx] = l;
}

__global__ __launch_bounds__(256) void prep_er(const float* __restrict__ Er) {
  int idx = blockIdx.x * 256 + threadIdx.x;
  __nv_bfloat16 h, l;
  pk1(Er[idx], h, l);
  g_erh[idx] = h;
  g_erl[idx] = l;
}

// ---------------------------------------------------------------------------
// QKV projection (unchanged).
// ---------------------------------------------------------------------------
#define WX 36
#define WW 36
#define QKV_WORDS (2 * 64 * WX + 2 * 192 * WW)
__global__ __launch_bounds__(256) void qkv_mma(const float* __restrict__ x) {
  extern __shared__ uint32_t qsm[];
  uint32_t* Xh = qsm;
  uint32_t* Xl = Xh + 64 * WX;
  uint32_t* WTh = Xl + 64 * WX;
  uint32_t* WTl = WTh + 192 * WW;
  int tid = threadIdx.x, w = tid >> 5, lane = tid & 31;
  int g = lane >> 2, tg = lane & 3;
  int row0 = blockIdx.x * 64;
  int mt = w & 3, nh = w >> 2;
  float acc[12][4] = {};

  for (int k0 = 0; k0 < CC; k0 += 64) {
    __syncthreads();
    for (int i = tid; i < 1024; i += 256) {
      int r = i >> 4, h4 = (i & 15) << 2;
      float4 v4 = *(const float4*)&x[(size_t)(row0 + r) * CC + k0 + h4];
      uint32_t h01, l01, h23, l23;
      pk(v4.x, v4.y, h01, l01);
      pk(v4.z, v4.w, h23, l23);
      int wc = r * WX + (h4 >> 1);
      *(uint2*)&Xh[wc] = make_uint2(h01, h23);
      *(uint2*)&Xl[wc] = make_uint2(l01, l23);
    }
    for (int i = tid; i < 1536; i += 256) {
      int n = i >> 3, w4 = (i & 7) << 2;
      int src = n * 256 + (k0 >> 1) + w4;
      *(uint4*)&WTh[n * WW + w4] = *(const uint4*)((const uint32_t*)g_wth + src);
      *(uint4*)&WTl[n * WW + w4] = *(const uint4*)((const uint32_t*)g_wtl + src);
    }
    __syncthreads();
    int r1 = 16 * mt + g, r2 = r1 + 8;
#pragma unroll
    for (int c4 = 0; c4 < 4; c4++) {
      int kw = 8 * c4;
      uint32_t ah[4], al[4];
      ah[0] = Xh[r1 * WX + kw + tg];
      ah[1] = Xh[r2 * WX + kw + tg];
      ah[2] = Xh[r1 * WX + kw + 4 + tg];
      ah[3] = Xh[r2 * WX + kw + 4 + tg];
      al[0] = Xl[r1 * WX + kw + tg];
      al[1] = Xl[r2 * WX + kw + tg];
      al[2] = Xl[r1 * WX + kw + 4 + tg];
      al[3] = Xl[r2 * WX + kw + 4 + tg];
#pragma unroll
      for (int v = 0; v < 12; v++) {
        int n = 8 * (12 * nh + v) + g;
        uint32_t bh0 = WTh[n * WW + kw + tg];
        uint32_t bh1 = WTh[n * WW + kw + 4 + tg];
        uint32_t bl0 = WTl[n * WW + kw + tg];
        uint32_t bl1 = WTl[n * WW + kw + 4 + tg];
        mmax2(acc[v], ah, al, bh0, bh1, bl0, bl1);
      }
    }
  }
  int r0g = row0 + 16 * mt + g;
#pragma unroll
  for (int v = 0; v < 12; v++) {
    int ncol = 8 * (12 * nh + v) + 2 * tg;
    int m = ncol >> 6, nn = ncol & 63;
    if (m < 2) {
      uint32_t* oh = (uint32_t*)(m == 0 ? g_qh : g_kh);
      uint32_t* ol = (uint32_t*)(m == 0 ? g_ql : g_kl);
      uint32_t h, l;
      pk(acc[v][0], acc[v][1], h, l);
      oh[(size_t)r0g * 32 + (nn >> 1)] = h;
      ol[(size_t)r0g * 32 + (nn >> 1)] = l;
      pk(acc[v][2], acc[v][3], h, l);
      oh[(size_t)(r0g + 8) * 32 + (nn >> 1)] = h;
      ol[(size_t)(r0g + 8) * 32 + (nn >> 1)] = l;
    } else {
      int bidx = r0g >> 11, t = r0g & 2047;
      size_t base = ((size_t)bidx * HH + nn) * TT + t;
      __nv_bfloat16 h, l;
      pk1(acc[v][0], h, l);
      g_vth[base] = h;
      g_vtl[base] = l;
      pk1(acc[v][1], h, l);
      g_vth[base + TT] = h;
      g_vtl[base + TT] = l;
      pk1(acc[v][2], h, l);
      g_vth[base + 8] = h;
      g_vtl[base + 8] = l;
      pk1(acc[v][3], h, l);
      g_vth[base + TT + 8] = h;
      g_vtl[base + TT + 8] = l;
    }
  }
}

// ---------------------------------------------------------------------------
// Fused attention: deferred-AV software pipeline, 2 barriers/iter.
//   phase1: AV(it-1) + S(it)/G(it) MMAs interleaved (all tensor work together)
//   phase2: softmax(it) on S-warps | cp.async prefetch(it+1) on G-warps
// ---------------------------------------------------------------------------
#define WB 36
#define WP 20
#define PG 104
#define VT (64 * WP)
#define ATTN_WORDS                                                     \
  (2 * 64 * WB + 4 * 32 * WB + 2 * 96 * WB + 4 * VT + 2 * 64 * WP + \
   32 * PG + 3 * 64)

__global__ __launch_bounds__(256, 2) void attn_mma(
    const float* __restrict__ Er, float* __restrict__ out) {
  extern __shared__ uint32_t sm[];
  uint32_t* Qh = sm;
  uint32_t* Ql = Qh + 64 * WB;
  uint32_t* Kh = Ql + 64 * WB;
  uint32_t* Kl = Kh + 32 * WB;
  uint32_t* Qrh = Kl + 32 * WB;
  uint32_t* Qrl = Qrh + 32 * WB;
  uint32_t* Erh = Qrl + 32 * WB;
  uint32_t* Erl = Erh + 96 * WB;
  uint32_t* Vth = Erl + 96 * WB;  // [2][64][WP]
  uint32_t* Vtl = Vth + 2 * VT;   // [2][64][WP]
  uint32_t* Ph = Vtl + 2 * VT;
  uint32_t* Pl = Ph + 64 * WP;
  float* Gs = (float*)(Pl + 64 * WP);  // 32 x PG
  float* ds = Gs + 32 * PG;
  float* as_ = ds + 64;
  float* lsm = as_ + 64;

  int tid = threadIdx.x, w = tid >> 5, lane = tid & 31;
  int g = lane >> 2, tg = lane & 3;
  int b = blockIdx.y;
  const uint4* QH4 = (const uint4*)g_qh + (size_t)b * TT * 8;
  const uint4* QL4 = (const uint4*)g_ql + (size_t)b * TT * 8;
  const uint4* KH4 = (const uint4*)g_kh + (size_t)b * TT * 8;
  const uint4* KL4 = (const uint4*)g_kl + (size_t)b * TT * 8;
  const uint4* VTH4 = (const uint4*)g_vth + (size_t)b * HH * 256;
  const uint4* VTL4 = (const uint4*)g_vtl + (size_t)b * HH * 256;
  const uint4* EH4 = (const uint4*)g_erh;
  const uint4* EL4 = (const uint4*)g_erl;

  uint32_t spKh = sptr(Kh), spKl = sptr(Kl);
  uint32_t spQrh = sptr(Qrh), spQrl = sptr(Qrl);
  uint32_t spErh = sptr(Erh), spErl = sptr(Erl);
  uint32_t spVth = sptr(Vth), spVtl = sptr(Vtl);

  int smt = w & 3, snh = w >> 2;

  int lrowA = lane & 15;
  int lcolA = ((lane >> 4) << 2);
  int lrowB = (lane & 7) + ((lane >> 4) << 3);
  int lcolB = ((lane >> 3) & 1) << 2;
  uint32_t aQh = sptr(Qh) + ((16 * w + lrowA) * WB + lcolA) * 4;
  uint32_t aQl = aQh + (uint32_t)(64 * WB * 4);
  uint32_t bKh = spKh + (lrowB * WB + lcolB) * 4;
  uint32_t bKl = bKh + (uint32_t)(32 * WB * 4);
  int gw = w - 4, mt2 = gw & 1, cg = gw >> 1;
  uint32_t aRh = spQrh + ((16 * mt2 + lrowA) * WB + lcolA) * 4;
  uint32_t aRl = aRh + (uint32_t)(32 * WB * 4);
  uint32_t bEh = spErh + ((48 * cg + lrowB) * WB + lcolB) * 4;
  uint32_t bEl = bEh + (uint32_t)(96 * WB * 4);
  uint32_t aPh = sptr(Ph) + ((16 * smt + lrowA) * WP + lcolA) * 4;
  uint32_t aPl = aPh + (uint32_t)(64 * WP * 4);
  uint32_t bVh0 = spVth + ((32 * snh + lrowB) * WP + lcolB) * 4;

  for (int half = 0; half < 2; half++) {
    int t0 = half == 0 ? blockIdx.x * 64 : (TT - 64 - blockIdx.x * 64);
    __syncthreads();
    for (int i = tid; i < 1024; i += 256) {  // Q tile
      int hl = i >> 9, rem = i & 511;
      int r = rem >> 3, k4 = (rem & 7) << 2;
      const uint4* src = hl ? QL4 : QH4;
      uint32_t* dst = hl ? Ql : Qh;
      *(uint4*)&dst[r * WB + k4] = src[(t0 + r) * 8 + (k4 >> 2)];
    }
    // Initial prefetch: K(s0=0), Qr, Vt buf0, Er 96 rows — cp.async
    {
      int rbase0 = t0 - 33;
      for (int i = tid; i < 3072; i += 256) {
        if (i < 1536) {
          int seg = i >> 9, rem = i & 511;
          int hl = rem >> 8, rem2 = rem & 255;
          if (seg == 0) {
            int r = rem2 >> 3, k4 = (rem2 & 7) << 2;
            cpa16((hl ? spKl : spKh) + (r * WB + k4) * 4,
                  (hl ? KL4 : KH4) + r * 8 + (k4 >> 2));
          } else if (seg == 1) {
            int r = rem2 >> 3, k4 = (rem2 & 7) << 2;
            cpa16((hl ? spQrl : spQrh) + (r * WB + k4) * 4,
                  (hl ? QL4 : QH4) + (1 + r) * 8 + (k4 >> 2));
          } else {
            int h = rem2 >> 2, t4 = (rem2 & 3) << 2;
            cpa16((hl ? spVtl : spVth) + (h * WP + t4) * 4,
                  (hl ? VTL4 : VTH4) + h * 256 + (t4 >> 2));
          }
        } else {
          int idx = i - 1536;
          int xr = idx >> 4, sub = idx & 15;
          int hl = sub >> 3, k4 = (sub & 7) << 2;
          int r = rbase0 + xr;
          int slot = (r + 2112) % 96;
          int rc = r < 0 ? 0 : r;
          cpa16((hl ? spErl : spErh) + (slot * WB + k4) * 4,
                (hl ? EL4 : EH4) + rc * 8 + (k4 >> 2));
        }
      }
      CP_COMMIT();
    }
    __syncthreads();  // Q visible for ds
    if (tid < 64) {
      const __nv_bfloat16* qh = (const __nv_bfloat16*)Qh + tid * 2 * WB;
      const __nv_bfloat16* ql = (const __nv_bfloat16*)Ql + tid * 2 * WB;
      const float* el = Er + (size_t)(TT - 1) * HH;
      float acc = 0.f;
#pragma unroll
      for (int h = 0; h < HH; h++)
        acc += (__bfloat162float(qh[h]) + __bfloat162float(ql[h])) * el[h];
      ds[tid] = acc;
    }

    float O[4][4] = {};
    float m_a = -1e30f, m_b = -1e30f, l_a = 0.f, l_b = 0.f;
    int niter = t0 / 32 + 2;

    for (int it = 0; it < niter; it++) {
      int s0 = it * 32;
      int rbase = t0 - s0 - 33;
      CP_WAIT0();
      __syncthreads();  // A: tiles + P/as_ of it-1 visible

      // ---- phase 1: AV(it-1) + S(it)/G(it) ----
      if (it > 0) {
        int pv = (it - 1) & 1;
        int r1 = 16 * smt + g, r2 = r1 + 8;
        float aa1 = as_[r1], aa2 = as_[r2];
#pragma unroll
        for (int v = 0; v < 4; v++) {
          O[v][0] *= aa1;
          O[v][1] *= aa1;
          O[v][2] *= aa2;
          O[v][3] *= aa2;
        }
        uint32_t vbh = bVh0 + (uint32_t)(pv * VT * 4);
        uint32_t vbl = vbh + (uint32_t)(2 * VT * 4);
#pragma unroll
        for (int c2 = 0; c2 < 2; c2++) {
          uint32_t kof = 32 * c2;
          uint32_t ah[4], al[4], bh[8], bl[8];
          ldm4(ah[0], ah[1], ah[2], ah[3], aPh + kof);
          ldm4(al[0], al[1], al[2], al[3], aPl + kof);
          ldm4(bh[0], bh[1], bh[2], bh[3], vbh + kof);
          ldm4(bh[4], bh[5], bh[6], bh[7], vbh + 16 * WP * 4 + kof);
          ldm4(bl[0], bl[1], bl[2], bl[3], vbl + kof);
          ldm4(bl[4], bl[5], bl[6], bl[7], vbl + 16 * WP * 4 + kof);
#pragma unroll
          for (int v = 0; v < 4; v++)
            mmax2(O[v], ah, al, bh[2 * v], bh[2 * v + 1], bl[2 * v],
                  bl[2 * v + 1]);
        }
      }

      float sf[4][4] = {};  // S fragments (warps 0-3)
      if (w < 4) {
#pragma unroll
        for (int c4 = 0; c4 < 4; c4++) {
          uint32_t kof = 32 * c4;
          uint32_t ah[4], al[4], bh[8], bl[8];
          ldm4(ah[0], ah[1], ah[2], ah[3], aQh + kof);
          ldm4(al[0], al[1], al[2], al[3], aQl + kof);
          ldm4(bh[0], bh[1], bh[2], bh[3], bKh + kof);
          ldm4(bh[4], bh[5], bh[6], bh[7], bKh + 16 * WB * 4 + kof);
          ldm4(bl[0], bl[1], bl[2], bl[3], bKl + kof);
          ldm4(bl[4], bl[5], bl[6], bl[7], bKl + 16 * WB * 4 + kof);
#pragma unroll
          for (int u = 0; u < 4; u++)
            mmax2(sf[u], ah, al, bh[2 * u], bh[2 * u + 1], bl[2 * u],
                  bl[2 * u + 1]);
        }
      } else {
        float gf[6][4] = {};
#pragma unroll
        for (int c4 = 0; c4 < 4; c4++) {
          uint32_t kof = 32 * c4;
          uint32_t ah[4], al[4], bh[12], bl[12];
          ldm4(ah[0], ah[1], ah[2], ah[3], aRh + kof);
          ldm4(al[0], al[1], al[2], al[3], aRl + kof);
          ldm4(bh[0], bh[1], bh[2], bh[3], bEh + kof);
          ldm4(bh[4], bh[5], bh[6], bh[7], bEh + 16 * WB * 4 + kof);
          ldm4(bh[8], bh[9], bh[10], bh[11], bEh + 32 * WB * 4 + kof);
          ldm4(bl[0], bl[1], bl[2], bl[3], bEl + kof);
          ldm4(bl[4], bl[5], bl[6], bl[7], bEl + 16 * WB * 4 + kof);
          ldm4(bl[8], bl[9], bl[10], bl[11], bEl + 32 * WB * 4 + kof);
#pragma unroll
          for (int v = 0; v < 6; v++)
            mmax2(gf[v], ah, al, bh[2 * v], bh[2 * v + 1], bl[2 * v],
                  bl[2 * v + 1]);
        }
        int r1 = 16 * mt2 + g, r2 = r1 + 8;
#pragma unroll
        for (int v = 0; v < 6; v++) {
          int n0 = 48 * cg + 8 * v + 2 * tg;
          *(float2*)&Gs[r1 * PG + n0] = make_float2(gf[v][0], gf[v][1]);
          *(float2*)&Gs[r2 * PG + n0] = make_float2(gf[v][2], gf[v][3]);
        }
      }
      __syncthreads();  // B: Gs ready; AV(it-1) done; buffers dead

      // ---- phase 2: prefetch(it+1) | softmax(it) ----
      if (it + 1 < niter) {
        int s0n = s0 + 32;
        int rbn = rbase - 32;
        int q = (it + 1) & 1;
#pragma unroll
        for (int ii = 0; ii < 8; ii++) {
          int i = tid + 256 * ii;
          int seg = i >> 9, rem = i & 511;
          int hl = rem >> 8, rem2 = rem & 255;
          if (seg == 0) {
            int r = rem2 >> 3, k4 = (rem2 & 7) << 2;
            cpa16((hl ? spKl : spKh) + (r * WB + k4) * 4,
                  (hl ? KL4 : KH4) + (s0n + r) * 8 + (k4 >> 2));
          } else if (seg == 1) {
            int r = rem2 >> 3, k4 = (rem2 & 7) << 2;
            int rq = s0n + 1 + r;
            if (rq > TT - 1) rq = TT - 1;  // clamped rows feed masked slots
            cpa16((hl ? spQrl : spQrh) + (r * WB + k4) * 4,
                  (hl ? QL4 : QH4) + rq * 8 + (k4 >> 2));
          } else if (seg == 2) {
            int h = rem2 >> 2, t4 = (rem2 & 3) << 2;
            cpa16((hl ? spVtl : spVth) + (q * VT + h * WP + t4) * 4,
                  (hl ? VTL4 : VTH4) + h * 256 + (s0n >> 3) + (t4 >> 2));
          } else {
            int xr = rem2 >> 3, k4 = (rem2 & 7) << 2;
            int r = rbn + xr;
            int slot = (r + 2112) % 96;
            int rc = r < 0 ? 0 : r;
            cpa16((hl ? spErl : spErh) + (slot * WB + k4) * 4,
                  (hl ? EL4 : EH4) + rc * 8 + (k4 >> 2));
          }
        }
        CP_COMMIT();
      }

      if (w < 4) {
        int ra = 16 * w + g, rb = ra + 8;
        int ta = t0 + ra, tb = t0 + rb;
        int bmA = (rbase + ra + 31 + 2112) % 96;
        int bmB = (rbase + rb + 31 + 2112) % 96;
        float va[8], vb[8];
        float dsa = ds[ra], dsb = ds[rb];
#pragma unroll
        for (int u = 0; u < 4; u++) {
#pragma unroll
          for (int e = 0; e < 2; e++) {
            int j = 8 * u + 2 * tg + e;
            int s = s0 + j;
            int sA = bmA - j;
            sA += (sA < 0) ? 96 : 0;
            int sB = bmB - j;
            sB += (sB < 0) ? 96 : 0;
            float adda = 0.f, addb = 0.f;
            if (s <= ta - 2)
              adda = Gs[j * PG + sA];
            else if (s == ta)
              adda = dsa;
            if (s <= tb - 2)
              addb = Gs[j * PG + sB];
            else if (s == tb)
              addb = dsb;
            float xa = SCALE * sf[u][e] + adda;
            float xb = SCALE * sf[u][2 + e] + addb;
            if (s > ta) xa = -1e30f;
            if (s > tb) xb = -1e30f;
            va[2 * u + e] = xa;
            vb[2 * u + e] = xb;
          }
        }
        float ma = va[0], mb = vb[0];
#pragma unroll
        for (int i = 1; i < 8; i++) {
          ma = fmaxf(ma, va[i]);
          mb = fmaxf(mb, vb[i]);
        }
        ma = fmaxf(ma, __shfl_xor_sync(0xffffffffu, ma, 1));
        ma = fmaxf(ma, __shfl_xor_sync(0xffffffffu, ma, 2));
        mb = fmaxf(mb, __shfl_xor_sync(0xffffffffu, mb, 1));
        mb = fmaxf(mb, __shfl_xor_sync(0xffffffffu, mb, 2));
        float mna = fmaxf(m_a, ma), mnb = fmaxf(m_b, mb);
        float ala = __expf(m_a - mna), alb = __expf(m_b - mnb);
        m_a = mna;
        m_b = mnb;
        float pa[8], pb[8];
        float rsa = 0.f, rsb = 0.f;
#pragma unroll
        for (int i = 0; i < 8; i++) {
          pa[i] = __expf(va[i] - mna);
          pb[i] = __expf(vb[i] - mnb);
          rsa += pa[i];
          rsb += pb[i];
        }
        rsa += __shfl_xor_sync(0xffffffffu, rsa, 1);
        rsa += __shfl_xor_sync(0xffffffffu, rsa, 2);
        rsb += __shfl_xor_sync(0xffffffffu, rsb, 1);
        rsb += __shfl_xor_sync(0xffffffffu, rsb, 2);
        l_a = ala * l_a + rsa;
        l_b = alb * l_b + rsb;
#pragma unroll
        for (int u = 0; u < 4; u++) {
          uint32_t h, l;
          pk(pa[2 * u], pa[2 * u + 1], h, l);
          Ph[ra * WP + 4 * u + tg] = h;
          Pl[ra * WP + 4 * u + tg] = l;
          pk(pb[2 * u], pb[2 * u + 1], h, l);
          Ph[rb * WP + 4 * u + tg] = h;
          Pl[rb * WP + 4 * u + tg] = l;
        }
        if (tg == 0) {
          as_[ra] = ala;
          as_[rb] = alb;
        }
      }
    }

    // tail: AV(niter-1)
    __syncthreads();
    {
      int pv = (niter - 1) & 1;
      int r1 = 16 * smt + g, r2 = r1 + 8;
      float aa1 = as_[r1], aa2 = as_[r2];
#pragma unroll
      for (int v = 0; v < 4; v++) {
        O[v][0] *= aa1;
        O[v][1] *= aa1;
        O[v][2] *= aa2;
        O[v][3] *= aa2;
      }
      uint32_t vbh = bVh0 + (uint32_t)(pv * VT * 4);
      uint32_t vbl = vbh + (uint32_t)(2 * VT * 4);
#pragma unroll
      for (int c2 = 0; c2 < 2; c2++) {
        uint32_t kof = 32 * c2;
        uint32_t ah[4], al[4], bh[8], bl[8];
        ldm4(ah[0], ah[1], ah[2], ah[3], aPh + kof);
        ldm4(al[0], al[1], al[2], al[3], aPl + kof);
        ldm4(bh[0], bh[1], bh[2], bh[3], vbh + kof);
        ldm4(bh[4], bh[5], bh[6], bh[7], vbh + 16 * WP * 4 + kof);
        ldm4(bl[0], bl[1], bl[2], bl[3], vbl + kof);
        ldm4(bl[4], bl[5], bl[6], bl[7], vbl + 16 * WP * 4 + kof);
#pragma unroll
        for (int v = 0; v < 4; v++)
          mmax2(O[v], ah, al, bh[2 * v], bh[2 * v + 1], bl[2 * v],
                bl[2 * v + 1]);
      }
    }

    if (w < 4 && tg == 0) {
      lsm[16 * w + g] = l_a;
      lsm[16 * w + g + 8] = l_b;
    }
    __syncthreads();
    int r1 = 16 * smt + g, r2 = r1 + 8;
    float inv1 = 1.f / lsm[r1], inv2 = 1.f / lsm[r2];
#pragma unroll
    for (int v = 0; v < 4; v++) {
      int nc = 32 * snh + 8 * v + 2 * tg;
      *(float2*)&out[((size_t)b * TT + t0 + r1) * HH + nc] =
          make_float2(O[v][0] * inv1, O[v][1] * inv1);
      *(float2*)&out[((size_t)b * TT + t0 + r2) * HH + nc] =
          make_float2(O[v][2] * inv2, O[v][3] * inv2);
    }
  }
}

extern "C" void kernel_launch(void* const* d_in, const int* in_sizes, int n_in,
                              void* d_out, int out_size) {
  (void)in_sizes;
  (void)n_in;
  (void)out_size;
  const float* x = (const float*)d_in[0];
  const float* Wq = (const float*)d_in[1];
  const float* Wk = (const float*)d_in[2];
  const float* Wv = (const float*)d_in[3];
  const float* Er = (const float*)d_in[4];
  float* out = (float*)d_out;

  cudaFuncSetAttribute(qkv_mma, cudaFuncAttributeMaxDynamicSharedMemorySize,
                       QKV_WORDS * 4);
  cudaFuncSetAttribute(attn_mma, cudaFuncAttributeMaxDynamicSharedMemorySize,
                       ATTN_WORDS * 4);

  prep_w<<<dim3(192 * 512 / 256), 256>>>(Wq, Wk, Wv);
  prep_er<<<dim3(TT * HH / 256), 256>>>(Er);
  qkv_mma<<<dim3((BB * TT) / 64), 256, QKV_WORDS * 4>>>(x);
  attn_mma<<<dim3(TT / 128, BB), 256, ATTN_WORDS * 4>>>(Er, out);
}

// round 17
// speedup vs baseline: 1.4910x; 1.0540x over previous
#include <cuda_runtime.h>
#include <cuda_bf16.h>
#include <cstdint>

#define BB 16
#define TT 2048
#define CC 512
#define HH 64
#define SCALE 0.125f

// Q,K split bf16 (packed pairs), row-major [b*T + t][64]
__device__ __nv_bfloat16 g_qh[BB * TT * HH];
__device__ __nv_bfloat16 g_ql[BB * TT * HH];
__device__ __nv_bfloat16 g_kh[BB * TT * HH];
__device__ __nv_bfloat16 g_kl[BB * TT * HH];
// V split + transposed: [b*64 + h][t]
__device__ __nv_bfloat16 g_vth[BB * HH * TT];
__device__ __nv_bfloat16 g_vtl[BB * HH * TT];
// Er split: [r][64]
__device__ __nv_bfloat16 g_erh[TT * HH];
__device__ __nv_bfloat16 g_erl[TT * HH];
// W transposed+split: [n (0..191)][k (0..511)]
__device__ __nv_bfloat16 g_wth[192 * 512];
__device__ __nv_bfloat16 g_wtl[192 * 512];

__device__ __forceinline__ void pk(float x, float y, uint32_t& h, uint32_t& l) {
  __nv_bfloat16 hx = __float2bfloat16(x), hy = __float2bfloat16(y);
  float rx = x - __bfloat162float(hx), ry = y - __bfloat162float(hy);
  __nv_bfloat16 lx = __float2bfloat16(rx), ly = __float2bfloat16(ry);
  h = (uint32_t)__bfloat16_as_ushort(hx) |
      ((uint32_t)__bfloat16_as_ushort(hy) << 16);
  l = (uint32_t)__bfloat16_as_ushort(lx) |
      ((uint32_t)__bfloat16_as_ushort(ly) << 16);
}
__device__ __forceinline__ void pk1(float x, __nv_bfloat16& h,
                                    __nv_bfloat16& l) {
  h = __float2bfloat16(x);
  l = __float2bfloat16(x - __bfloat162float(h));
}

__device__ __forceinline__ void mma16(float* c, uint32_t a0, uint32_t a1,
                                      uint32_t a2, uint32_t a3, uint32_t b0,
                                      uint32_t b1) {
  asm volatile(
      "mma.sync.aligned.m16n8k16.row.col.f32.bf16.bf16.f32 "
      "{%0,%1,%2,%3}, {%4,%5,%6,%7}, {%8,%9}, {%0,%1,%2,%3};"
      : "+f"(c[0]), "+f"(c[1]), "+f"(c[2]), "+f"(c[3])
      : "r"(a0), "r"(a1), "r"(a2), "r"(a3), "r"(b0), "r"(b1));
}
__device__ __forceinline__ void mmax2(float* c, const uint32_t* ah,
                                      const uint32_t* al, uint32_t bh0,
                                      uint32_t bh1, uint32_t bl0,
                                      uint32_t bl1) {
  mma16(c, ah[0], ah[1], ah[2], ah[3], bl0, bl1);
  mma16(c, al[0], al[1], al[2], al[3], bh0, bh1);
  mma16(c, ah[0], ah[1], ah[2], ah[3], bh0, bh1);
}

__device__ __forceinline__ void ldm4(uint32_t& r0, uint32_t& r1, uint32_t& r2,
                                     uint32_t& r3, uint32_t addr) {
  asm volatile(
      "ldmatrix.sync.aligned.m8n8.x4.shared.b16 {%0,%1,%2,%3}, [%4];"
      : "=r"(r0), "=r"(r1), "=r"(r2), "=r"(r3)
      : "r"(addr));
}
__device__ __forceinline__ uint32_t sptr(const void* p) {
  return (uint32_t)__cvta_generic_to_shared(p);
}
__device__ __forceinline__ void cpa16(uint32_t saddr, const void* gaddr) {
  asm volatile("cp.async.cg.shared.global [%0], [%1], 16;\n" ::"r"(saddr),
               "l"(gaddr));
}
#define CP_COMMIT() asm volatile("cp.async.commit_group;\n" ::: "memory")
#define CP_WAIT0() asm volatile("cp.async.wait_group 0;\n" ::: "memory")

// ---------------------------------------------------------------------------
// One-shot prep (fused): W split+transpose, Er split.
// Blocks [0,384): W. Blocks [384,896): Er.
// ---------------------------------------------------------------------------
__global__ __launch_bounds__(256) void prep_all(const float* __restrict__ Wq,
                                                const float* __restrict__ Wk,
                                                const float* __restrict__ Wv,
                                                const float* __restrict__ Er) {
  if (blockIdx.x < 384) {
    int idx = blockIdx.x * 256 + threadIdx.x;  // 192*512
    int n = idx >> 9, k = idx & 511;
    const float* Wm = n < 64 ? Wq : (n < 128 ? Wk : Wv);
    float v = Wm[(size_t)k * HH + (n & 63)];
    __nv_bfloat16 h, l;
    pk1(v, h, l);
    g_wth[idx] = h;
    g_wtl[idx] = l;
  } else {
    int idx = (blockIdx.x - 384) * 256 + threadIdx.x;  // TT*HH
    __nv_bfloat16 h, l;
    pk1(Er[idx], h, l);
    g_erh[idx] = h;
    g_erl[idx] = l;
  }
}

// ---------------------------------------------------------------------------
// QKV projection: double-buffered cp.async pipeline.
//   W tiles: cp.async pure copies (pre-split). X: LDG->regs prefetch, split
//   after the MMA into the alternate buffer.
// ---------------------------------------------------------------------------
#define WX 36
#define WW 36
#define XB (64 * WX)
#define WTB (192 * WW)
#define QKV_WORDS (2 * 2 * XB + 2 * 2 * WTB)
__global__ __launch_bounds__(256) void qkv_mma(const float* __restrict__ x) {
  extern __shared__ uint32_t qsm[];
  uint32_t* Xh = qsm;             // [2][XB]
  uint32_t* Xl = Xh + 2 * XB;     // [2][XB]
  uint32_t* WTh = Xl + 2 * XB;    // [2][WTB]
  uint32_t* WTl = WTh + 2 * WTB;  // [2][WTB]
  uint32_t spWTh = sptr(WTh), spWTl = sptr(WTl);
  int tid = threadIdx.x, w = tid >> 5, lane = tid & 31;
  int g = lane >> 2, tg = lane & 3;
  int row0 = blockIdx.x * 64;
  int mt = w & 3, nh = w >> 2;
  float acc[12][4] = {};
  float4 xr[4];

  // X element indices for this thread's 4 prefetch slots
  int xrow[4], xcol[4];
#pragma unroll
  for (int ii = 0; ii < 4; ii++) {
    int i = tid + 256 * ii;
    xrow[ii] = i >> 4;
    xcol[ii] = (i & 15) << 2;
  }

  // ---- prologue: chunk 0 ----
#pragma unroll
  for (int ii = 0; ii < 4; ii++)
    xr[ii] = *(const float4*)&x[(size_t)(row0 + xrow[ii]) * CC + xcol[ii]];
  for (int i = tid; i < 1536; i += 256) {
    int n = i >> 3, w4 = (i & 7) << 2;
    int src = n * 256 + w4;
    cpa16(spWTh + (n * WW + w4) * 4, (const uint32_t*)g_wth + src);
    cpa16(spWTl + (n * WW + w4) * 4, (const uint32_t*)g_wtl + src);
  }
  CP_COMMIT();
#pragma unroll
  for (int ii = 0; ii < 4; ii++) {
    uint32_t h01, l01, h23, l23;
    pk(xr[ii].x, xr[ii].y, h01, l01);
    pk(xr[ii].z, xr[ii].w, h23, l23);
    int wc = xrow[ii] * WX + (xcol[ii] >> 1);
    *(uint2*)&Xh[wc] = make_uint2(h01, h23);
    *(uint2*)&Xl[wc] = make_uint2(l01, l23);
  }

  for (int c = 0; c < 8; c++) {
    CP_WAIT0();
    __syncthreads();  // chunk c tiles visible

    // prefetch chunk c+1: X into regs, W via cp.async into alt buffer
    if (c < 7) {
      int k0n = (c + 1) * 64;
      int nb = (c + 1) & 1;
#pragma unroll
      for (int ii = 0; ii < 4; ii++)
        xr[ii] =
            *(const float4*)&x[(size_t)(row0 + xrow[ii]) * CC + k0n + xcol[ii]];
      for (int i = tid; i < 1536; i += 256) {
        int n = i >> 3, w4 = (i & 7) << 2;
        int src = n * 256 + (k0n >> 1) + w4;
        cpa16(spWTh + (nb * WTB + n * WW + w4) * 4,
              (const uint32_t*)g_wth + src);
        cpa16(spWTl + (nb * WTB + n * WW + w4) * 4,
              (const uint32_t*)g_wtl + src);
      }
      CP_COMMIT();
    }

    // MMA on chunk c
    int cb = c & 1;
    uint32_t* Xhc = Xh + cb * XB;
    uint32_t* Xlc = Xl + cb * XB;
    uint32_t* WThc = WTh + cb * WTB;
    uint32_t* WTlc = WTl + cb * WTB;
    int r1 = 16 * mt + g, r2 = r1 + 8;
#pragma unroll
    for (int c4 = 0; c4 < 4; c4++) {
      int kw = 8 * c4;
      uint32_t ah[4], al[4];
      ah[0] = Xhc[r1 * WX + kw + tg];
      ah[1] = Xhc[r2 * WX + kw + tg];
      ah[2] = Xhc[r1 * WX + kw + 4 + tg];
      ah[3] = Xhc[r2 * WX + kw + 4 + tg];
      al[0] = Xlc[r1 * WX + kw + tg];
      al[1] = Xlc[r2 * WX + kw + tg];
      al[2] = Xlc[r1 * WX + kw + 4 + tg];
      al[3] = Xlc[r2 * WX + kw + 4 + tg];
#pragma unroll
      for (int v = 0; v < 12; v++) {
        int n = 8 * (12 * nh + v) + g;
        uint32_t bh0 = WThc[n * WW + kw + tg];
        uint32_t bh1 = WThc[n * WW + kw + 4 + tg];
        uint32_t bl0 = WTlc[n * WW + kw + tg];
        uint32_t bl1 = WTlc[n * WW + kw + 4 + tg];
        mmax2(acc[v], ah, al, bh0, bh1, bl0, bl1);
      }
    }

    // store prefetched X(c+1) into alternate buffer
    if (c < 7) {
      int nb = (c + 1) & 1;
#pragma unroll
      for (int ii = 0; ii < 4; ii++) {
        uint32_t h01, l01, h23, l23;
        pk(xr[ii].x, xr[ii].y, h01, l01);
        pk(xr[ii].z, xr[ii].w, h23, l23);
        int wc = nb * XB + xrow[ii] * WX + (xcol[ii] >> 1);
        *(uint2*)&Xh[wc] = make_uint2(h01, h23);
        *(uint2*)&Xl[wc] = make_uint2(l01, l23);
      }
    }
  }

  int r0g = row0 + 16 * mt + g;
#pragma unroll
  for (int v = 0; v < 12; v++) {
    int ncol = 8 * (12 * nh + v) + 2 * tg;
    int m = ncol >> 6, nn = ncol & 63;
    if (m < 2) {
      uint32_t* oh = (uint32_t*)(m == 0 ? g_qh : g_kh);
      uint32_t* ol = (uint32_t*)(m == 0 ? g_ql : g_kl);
      uint32_t h, l;
      pk(acc[v][0], acc[v][1], h, l);
      oh[(size_t)r0g * 32 + (nn >> 1)] = h;
      ol[(size_t)r0g * 32 + (nn >> 1)] = l;
      pk(acc[v][2], acc[v][3], h, l);
      oh[(size_t)(r0g + 8) * 32 + (nn >> 1)] = h;
      ol[(size_t)(r0g + 8) * 32 + (nn >> 1)] = l;
    } else {
      int bidx = r0g >> 11, t = r0g & 2047;
      size_t base = ((size_t)bidx * HH + nn) * TT + t;
      __nv_bfloat16 h, l;
      pk1(acc[v][0], h, l);
      g_vth[base] = h;
      g_vtl[base] = l;
      pk1(acc[v][1], h, l);
      g_vth[base + TT] = h;
      g_vtl[base + TT] = l;
      pk1(acc[v][2], h, l);
      g_vth[base + 8] = h;
      g_vtl[base + 8] = l;
      pk1(acc[v][3], h, l);
      g_vth[base + TT + 8] = h;
      g_vtl[base + TT + 8] = l;
    }
  }
}

// ---------------------------------------------------------------------------
// Fused attention: deferred-AV software pipeline, 2 barriers/iter (round 16).
// ---------------------------------------------------------------------------
#define WB 36
#define WP 20
#define PG 104
#define VT (64 * WP)
#define ATTN_WORDS                                                     \
  (2 * 64 * WB + 4 * 32 * WB + 2 * 96 * WB + 4 * VT + 2 * 64 * WP + \
   32 * PG + 3 * 64)

__global__ __launch_bounds__(256, 2) void attn_mma(
    const float* __restrict__ Er, float* __restrict__ out) {
  extern __shared__ uint32_t sm[];
  uint32_t* Qh = sm;
  uint32_t* Ql = Qh + 64 * WB;
  uint32_t* Kh = Ql + 64 * WB;
  uint32_t* Kl = Kh + 32 * WB;
  uint32_t* Qrh = Kl + 32 * WB;
  uint32_t* Qrl = Qrh + 32 * WB;
  uint32_t* Erh = Qrl + 32 * WB;
  uint32_t* Erl = Erh + 96 * WB;
  uint32_t* Vth = Erl + 96 * WB;  // [2][64][WP]
  uint32_t* Vtl = Vth + 2 * VT;   // [2][64][WP]
  uint32_t* Ph = Vtl + 2 * VT;
  uint32_t* Pl = Ph + 64 * WP;
  float* Gs = (float*)(Pl + 64 * WP);  // 32 x PG
  float* ds = Gs + 32 * PG;
  float* as_ = ds + 64;
  float* lsm = as_ + 64;

  int tid = threadIdx.x, w = tid >> 5, lane = tid & 31;
  int g = lane >> 2, tg = lane & 3;
  int b = blockIdx.y;
  const uint4* QH4 = (const uint4*)g_qh + (size_t)b * TT * 8;
  const uint4* QL4 = (const uint4*)g_ql + (size_t)b * TT * 8;
  const uint4* KH4 = (const uint4*)g_kh + (size_t)b * TT * 8;
  const uint4* KL4 = (const uint4*)g_kl + (size_t)b * TT * 8;
  const uint4* VTH4 = (const uint4*)g_vth + (size_t)b * HH * 256;
  const uint4* VTL4 = (const uint4*)g_vtl + (size_t)b * HH * 256;
  const uint4* EH4 = (const uint4*)g_erh;
  const uint4* EL4 = (const uint4*)g_erl;

  uint32_t spKh = sptr(Kh), spKl = sptr(Kl);
  uint32_t spQrh = sptr(Qrh), spQrl = sptr(Qrl);
  uint32_t spErh = sptr(Erh), spErl = sptr(Erl);
  uint32_t spVth = sptr(Vth), spVtl = sptr(Vtl);

  int smt = w & 3, snh = w >> 2;

  int lrowA = lane & 15;
  int lcolA = ((lane >> 4) << 2);
  int lrowB = (lane & 7) + ((lane >> 4) << 3);
  int lcolB = ((lane >> 3) & 1) << 2;
  uint32_t aQh = sptr(Qh) + ((16 * w + lrowA) * WB + lcolA) * 4;
  uint32_t aQl = aQh + (uint32_t)(64 * WB * 4);
  uint32_t bKh = spKh + (lrowB * WB + lcolB) * 4;
  uint32_t bKl = bKh + (uint32_t)(32 * WB * 4);
  int gw = w - 4, mt2 = gw & 1, cg = gw >> 1;
  uint32_t aRh = spQrh + ((16 * mt2 + lrowA) * WB + lcolA) * 4;
  uint32_t aRl = aRh + (uint32_t)(32 * WB * 4);
  uint32_t bEh = spErh + ((48 * cg + lrowB) * WB + lcolB) * 4;
  uint32_t bEl = bEh + (uint32_t)(96 * WB * 4);
  uint32_t aPh = sptr(Ph) + ((16 * smt + lrowA) * WP + lcolA) * 4;
  uint32_t aPl = aPh + (uint32_t)(64 * WP * 4);
  uint32_t bVh0 = spVth + ((32 * snh + lrowB) * WP + lcolB) * 4;

  for (int half = 0; half < 2; half++) {
    int t0 = half == 0 ? blockIdx.x * 64 : (TT - 64 - blockIdx.x * 64);
    __syncthreads();
    for (int i = tid; i < 1024; i += 256) {  // Q tile
      int hl = i >> 9, rem = i & 511;
      int r = rem >> 3, k4 = (rem & 7) << 2;
      const uint4* src = hl ? QL4 : QH4;
      uint32_t* dst = hl ? Ql : Qh;
      *(uint4*)&dst[r * WB + k4] = src[(t0 + r) * 8 + (k4 >> 2)];
    }
    // Initial prefetch: K(s0=0), Qr, Vt buf0, Er 96 rows — cp.async
    {
      int rbase0 = t0 - 33;
      for (int i = tid; i < 3072; i += 256) {
        if (i < 1536) {
          int seg = i >> 9, rem = i & 511;
          int hl = rem >> 8, rem2 = rem & 255;
          if (seg == 0) {
            int r = rem2 >> 3, k4 = (rem2 & 7) << 2;
            cpa16((hl ? spKl : spKh) + (r * WB + k4) * 4,
                  (hl ? KL4 : KH4) + r * 8 + (k4 >> 2));
          } else if (seg == 1) {
            int r = rem2 >> 3, k4 = (rem2 & 7) << 2;
            cpa16((hl ? spQrl : spQrh) + (r * WB + k4) * 4,
                  (hl ? QL4 : QH4) + (1 + r) * 8 + (k4 >> 2));
          } else {
            int h = rem2 >> 2, t4 = (rem2 & 3) << 2;
            cpa16((hl ? spVtl : spVth) + (h * WP + t4) * 4,
                  (hl ? VTL4 : VTH4) + h * 256 + (t4 >> 2));
          }
        } else {
          int idx = i - 1536;
          int xr = idx >> 4, sub = idx & 15;
          int hl = sub >> 3, k4 = (sub & 7) << 2;
          int r = rbase0 + xr;
          int slot = (r + 2112) % 96;
          int rc = r < 0 ? 0 : r;
          cpa16((hl ? spErl : spErh) + (slot * WB + k4) * 4,
                (hl ? EL4 : EH4) + rc * 8 + (k4 >> 2));
        }
      }
      CP_COMMIT();
    }
    __syncthreads();  // Q visible for ds
    if (tid < 64) {
      const __nv_bfloat16* qh = (const __nv_bfloat16*)Qh + tid * 2 * WB;
      const __nv_bfloat16* ql = (const __nv_bfloat16*)Ql + tid * 2 * WB;
      const float* el = Er + (size_t)(TT - 1) * HH;
      float acc = 0.f;
#pragma unroll
      for (int h = 0; h < HH; h++)
        acc += (__bfloat162float(qh[h]) + __bfloat162float(ql[h])) * el[h];
      ds[tid] = acc;
    }

    float O[4][4] = {};
    float m_a = -1e30f, m_b = -1e30f, l_a = 0.f, l_b = 0.f;
    int niter = t0 / 32 + 2;

    for (int it = 0; it < niter; it++) {
      int s0 = it * 32;
      int rbase = t0 - s0 - 33;
      CP_WAIT0();
      __syncthreads();  // A: tiles + P/as_ of it-1 visible

      // ---- phase 1: AV(it-1) + S(it)/G(it) ----
      if (it > 0) {
        int pv = (it - 1) & 1;
        int r1 = 16 * smt + g, r2 = r1 + 8;
        float aa1 = as_[r1], aa2 = as_[r2];
#pragma unroll
        for (int v = 0; v < 4; v++) {
          O[v][0] *= aa1;
          O[v][1] *= aa1;
          O[v][2] *= aa2;
          O[v][3] *= aa2;
        }
        uint32_t vbh = bVh0 + (uint32_t)(pv * VT * 4);
        uint32_t vbl = vbh + (uint32_t)(2 * VT * 4);
#pragma unroll
        for (int c2 = 0; c2 < 2; c2++) {
          uint32_t kof = 32 * c2;
          uint32_t ah[4], al[4], bh[8], bl[8];
          ldm4(ah[0], ah[1], ah[2], ah[3], aPh + kof);
          ldm4(al[0], al[1], al[2], al[3], aPl + kof);
          ldm4(bh[0], bh[1], bh[2], bh[3], vbh + kof);
          ldm4(bh[4], bh[5], bh[6], bh[7], vbh + 16 * WP * 4 + kof);
          ldm4(bl[0], bl[1], bl[2], bl[3], vbl + kof);
          ldm4(bl[4], bl[5], bl[6], bl[7], vbl + 16 * WP * 4 + kof);
#pragma unroll
          for (int v = 0; v < 4; v++)
            mmax2(O[v], ah, al, bh[2 * v], bh[2 * v + 1], bl[2 * v],
                  bl[2 * v + 1]);
        }
      }

      float sf[4][4] = {};  // S fragments (warps 0-3)
      if (w < 4) {
#pragma unroll
        for (int c4 = 0; c4 < 4; c4++) {
          uint32_t kof = 32 * c4;
          uint32_t ah[4], al[4], bh[8], bl[8];
          ldm4(ah[0], ah[1], ah[2], ah[3], aQh + kof);
          ldm4(al[0], al[1], al[2], al[3], aQl + kof);
          ldm4(bh[0], bh[1], bh[2], bh[3], bKh + kof);
          ldm4(bh[4], bh[5], bh[6], bh[7], bKh + 16 * WB * 4 + kof);
          ldm4(bl[0], bl[1], bl[2], bl[3], bKl + kof);
          ldm4(bl[4], bl[5], bl[6], bl[7], bKl + 16 * WB * 4 + kof);
#pragma unroll
          for (int u = 0; u < 4; u++)
            mmax2(sf[u], ah, al, bh[2 * u], bh[2 * u + 1], bl[2 * u],
                  bl[2 * u + 1]);
        }
      } else {
        float gf[6][4] = {};
#pragma unroll
        for (int c4 = 0; c4 < 4; c4++) {
          uint32_t kof = 32 * c4;
          uint32_t ah[4], al[4], bh[12], bl[12];
          ldm4(ah[0], ah[1], ah[2], ah[3], aRh + kof);
          ldm4(al[0], al[1], al[2], al[3], aRl + kof);
          ldm4(bh[0], bh[1], bh[2], bh[3], bEh + kof);
          ldm4(bh[4], bh[5], bh[6], bh[7], bEh + 16 * WB * 4 + kof);
          ldm4(bh[8], bh[9], bh[10], bh[11], bEh + 32 * WB * 4 + kof);
          ldm4(bl[0], bl[1], bl[2], bl[3], bEl + kof);
          ldm4(bl[4], bl[5], bl[6], bl[7], bEl + 16 * WB * 4 + kof);
          ldm4(bl[8], bl[9], bl[10], bl[11], bEl + 32 * WB * 4 + kof);
#pragma unroll
          for (int v = 0; v < 6; v++)
            mmax2(gf[v], ah, al, bh[2 * v], bh[2 * v + 1], bl[2 * v],
                  bl[2 * v + 1]);
        }
        int r1 = 16 * mt2 + g, r2 = r1 + 8;
#pragma unroll
        for (int v = 0; v < 6; v++) {
          int n0 = 48 * cg + 8 * v + 2 * tg;
          *(float2*)&Gs[r1 * PG + n0] = make_float2(gf[v][0], gf[v][1]);
          *(float2*)&Gs[r2 * PG + n0] = make_float2(gf[v][2], gf[v][3]);
        }
      }
      __syncthreads();  // B: Gs ready; AV(it-1) done; buffers dead

      // ---- phase 2: prefetch(it+1) | softmax(it) ----
      if (it + 1 < niter) {
        int s0n = s0 + 32;
        int rbn = rbase - 32;
        int q = (it + 1) & 1;
#pragma unroll
        for (int ii = 0; ii < 8; ii++) {
          int i = tid + 256 * ii;
          int seg = i >> 9, rem = i & 511;
          int hl = rem >> 8, rem2 = rem & 255;
          if (seg == 0) {
            int r = rem2 >> 3, k4 = (rem2 & 7) << 2;
            cpa16((hl ? spKl : spKh) + (r * WB + k4) * 4,
                  (hl ? KL4 : KH4) + (s0n + r) * 8 + (k4 >> 2));
          } else if (seg == 1) {
            int r = rem2 >> 3, k4 = (rem2 & 7) << 2;
            int rq = s0n + 1 + r;
            if (rq > TT - 1) rq = TT - 1;  // clamped rows feed masked slots
            cpa16((hl ? spQrl : spQrh) + (r * WB + k4) * 4,
                  (hl ? QL4 : QH4) + rq * 8 + (k4 >> 2));
          } else if (seg == 2) {
            int h = rem2 >> 2, t4 = (rem2 & 3) << 2;
            cpa16((hl ? spVtl : spVth) + (q * VT + h * WP + t4) * 4,
                  (hl ? VTL4 : VTH4) + h * 256 + (s0n >> 3) + (t4 >> 2));
          } else {
            int xr = rem2 >> 3, k4 = (rem2 & 7) << 2;
            int r = rbn + xr;
            int slot = (r + 2112) % 96;
            int rc = r < 0 ? 0 : r;
            cpa16((hl ? spErl : spErh) + (slot * WB + k4) * 4,
                  (hl ? EL4 : EH4) + rc * 8 + (k4 >> 2));
          }
        }
        CP_COMMIT();
      }

      if (w < 4) {
        int ra = 16 * w + g, rb = ra + 8;
        int ta = t0 + ra, tb = t0 + rb;
        int bmA = (rbase + ra + 31 + 2112) % 96;
        int bmB = (rbase + rb + 31 + 2112) % 96;
        float va[8], vb[8];
        float dsa = ds[ra], dsb = ds[rb];
#pragma unroll
        for (int u = 0; u < 4; u++) {
#pragma unroll
          for (int e = 0; e < 2; e++) {
            int j = 8 * u + 2 * tg + e;
            int s = s0 + j;
            int sA = bmA - j;
            sA += (sA < 0) ? 96 : 0;
            int sB = bmB - j;
            sB += (sB < 0) ? 96 : 0;
            float adda = 0.f, addb = 0.f;
            if (s <= ta - 2)
              adda = Gs[j * PG + sA];
            else if (s == ta)
              adda = dsa;
            if (s <= tb - 2)
              addb = Gs[j * PG + sB];
            else if (s == tb)
              addb = dsb;
            float xa = SCALE * sf[u][e] + adda;
            float xb = SCALE * sf[u][2 + e] + addb;
            if (s > ta) xa = -1e30f;
            if (s > tb) xb = -1e30f;
            va[2 * u + e] = xa;
            vb[2 * u + e] = xb;
          }
        }
        float ma = va[0], mb = vb[0];
#pragma unroll
        for (int i = 1; i < 8; i++) {
          ma = fmaxf(ma, va[i]);
          mb = fmaxf(mb, vb[i]);
        }
        ma = fmaxf(ma, __shfl_xor_sync(0xffffffffu, ma, 1));
        ma = fmaxf(ma, __shfl_xor_sync(0xffffffffu, ma, 2));
        mb = fmaxf(mb, __shfl_xor_sync(0xffffffffu, mb, 1));
        mb = fmaxf(mb, __shfl_xor_sync(0xffffffffu, mb, 2));
        float mna = fmaxf(m_a, ma), mnb = fmaxf(m_b, mb);
        float ala = __expf(m_a - mna), alb = __expf(m_b - mnb);
        m_a = mna;
        m_b = mnb;
        float pa[8], pb[8];
        float rsa = 0.f, rsb = 0.f;
#pragma unroll
        for (int i = 0; i < 8; i++) {
          pa[i] = __expf(va[i] - mna);
          pb[i] = __expf(vb[i] - mnb);
          rsa += pa[i];
          rsb += pb[i];
        }
        rsa += __shfl_xor_sync(0xffffffffu, rsa, 1);
        rsa += __shfl_xor_sync(0xffffffffu, rsa, 2);
        rsb += __shfl_xor_sync(0xffffffffu, rsb, 1);
        rsb += __shfl_xor_sync(0xffffffffu, rsb, 2);
        l_a = ala * l_a + rsa;
        l_b = alb * l_b + rsb;
#pragma unroll
        for (int u = 0; u < 4; u++) {
          uint32_t h, l;
          pk(pa[2 * u], pa[2 * u + 1], h, l);
          Ph[ra * WP + 4 * u + tg] = h;
          Pl[ra * WP + 4 * u + tg] = l;
          pk(pb[2 * u], pb[2 * u + 1], h, l);
          Ph[rb * WP + 4 * u + tg] = h;
          Pl[rb * WP + 4 * u + tg] = l;
        }
        if (tg == 0) {
          as_[ra] = ala;
          as_[rb] = alb;
        }
      }
    }

    // tail: AV(niter-1)
    __syncthreads();
    {
      int pv = (niter - 1) & 1;
      int r1 = 16 * smt + g, r2 = r1 + 8;
      float aa1 = as_[r1], aa2 = as_[r2];
#pragma unroll
      for (int v = 0; v < 4; v++) {
        O[v][0] *= aa1;
        O[v][1] *= aa1;
        O[v][2] *= aa2;
        O[v][3] *= aa2;
      }
      uint32_t vbh = bVh0 + (uint32_t)(pv * VT * 4);
      uint32_t vbl = vbh + (uint32_t)(2 * VT * 4);
#pragma unroll
      for (int c2 = 0; c2 < 2; c2++) {
        uint32_t kof = 32 * c2;
        uint32_t ah[4], al[4], bh[8], bl[8];
        ldm4(ah[0], ah[1], ah[2], ah[3], aPh + kof);
        ldm4(al[0], al[1], al[2], al[3], aPl + kof);
        ldm4(bh[0], bh[1], bh[2], bh[3], vbh + kof);
        ldm4(bh[4], bh[5], bh[6], bh[7], vbh + 16 * WP * 4 + kof);
        ldm4(bl[0], bl[1], bl[2], bl[3], vbl + kof);
        ldm4(bl[4], bl[5], bl[6], bl[7], vbl + 16 * WP * 4 + kof);
#pragma unroll
        for (int v = 0; v < 4; v++)
          mmax2(O[v], ah, al, bh[2 * v], bh[2 * v + 1], bl[2 * v],
                bl[2 * v + 1]);
      }
    }

    if (w < 4 && tg == 0) {
      lsm[16 * w + g] = l_a;
      lsm[16 * w + g + 8] = l_b;
    }
    __syncthreads();
    int r1 = 16 * smt + g, r2 = r1 + 8;
    float inv1 = 1.f / lsm[r1], inv2 = 1.f / lsm[r2];
#pragma unroll
    for (int v = 0; v < 4; v++) {
      int nc = 32 * snh + 8 * v + 2 * tg;
      *(float2*)&out[((size_t)b * TT + t0 + r1) * HH + nc] =
          make_float2(O[v][0] * inv1, O[v][1] * inv1);
      *(float2*)&out[((size_t)b * TT + t0 + r2) * HH + nc] =
          make_float2(O[v][2] * inv2, O[v][3] * inv2);
    }
  }
}

extern "C" void kernel_launch(void* const* d_in, const int* in_sizes, int n_in,
                              void* d_out, int out_size) {
  (void)in_sizes;
  (void)n_in;
  (void)out_size;
  const float* x = (const float*)d_in[0];
  const float* Wq = (const float*)d_in[1];
  const float* Wk = (const float*)d_in[2];
  const float* Wv = (const float*)d_in[3];
  const float* Er = (const float*)d_in[4];
  float* out = (float*)d_out;

  cudaFuncSetAttribute(qkv_mma, cudaFuncAttributeMaxDynamicSharedMemorySize,
                       QKV_WORDS * 4);
  cudaFuncSetAttribute(attn_mma, cudaFuncAttributeMaxDynamicSharedMemorySize,
                       ATTN_WORDS * 4);

  prep_all<<<dim3(896), 256>>>(Wq, Wk, Wv, Er);
  qkv_mma<<<dim3((BB * TT) / 64), 256, QKV_WORDS * 4>>>(x);
  attn_mma<<<dim3(TT / 128, BB), 256, ATTN_WORDS * 4>>>(Er, out);
}